// round 6
// baseline (speedup 1.0000x reference)
#include <cuda_runtime.h>
#include <cuda_bf16.h>
#include <cstdint>

#define BB  8
#define N0  8192
#define NP  2048
#define CPf 512
#define CSf 256
#define C1f 256
#define C2f 256
#define KW  768   // CP+CS

// smem row: 64 bf16 hi (128B) | 64 bf16 lo (128B) | pad 16B
#define PITCH 272
#define O_AS   0
#define O_BS   34816              // 128*PITCH
#define STAGE  69632              // one stage = A tile + B tile
#define SM_BYTES (2*STAGE)        // double buffered
// epilogue overlays (inside stage 0, used after mainloop)
#define O_SBUF 0                  // 32 x 132 floats
#define O_SID  16896
#define O_SWT  18432
#define O_CHS  19968
#define O_CHQ  20480

// ---------------- scratch (device globals) ----------------
__device__ int   g_idx[BB*N0*3];
__device__ float g_wt [BB*N0*3];
__device__ float g_Gt [BB*NP*C1f];
__device__ float g_y1 [BB*C1f*N0];
__device__ float g_z  [BB*C2f*N0];
__device__ float g_p1 [C1f*512], g_p2[C1f*512];
__device__ float g_sc1[C1f], g_bi1[C1f], g_sc2[C2f], g_bi2[C2f];
// pre-converted bf16 hi/lo operands ([row][k] GEMM-ready layout)
__device__ __align__(16) __nv_bfloat16 g_fA_hi[BB*NP*CPf], g_fA_lo[BB*NP*CPf];
__device__ __align__(16) __nv_bfloat16 g_fS_hi[BB*N0*CSf], g_fS_lo[BB*N0*CSf];
__device__ __align__(16) __nv_bfloat16 g_yb_hi[BB*N0*C1f], g_yb_lo[BB*N0*C1f];
__device__ __align__(16) __nv_bfloat16 g_W1_hi[C1f*KW],    g_W1_lo[C1f*KW];
__device__ __align__(16) __nv_bfloat16 g_W2_hi[C2f*C1f],   g_W2_lo[C2f*C1f];

// ---------------- PTX wrappers (baseline ISA, compute_103-safe) ----------------
__device__ __forceinline__ uint32_t smem_u32(const void* p) {
    uint32_t a;
    asm("{ .reg .u64 t; cvta.to.shared.u64 t, %1; cvt.u32.u64 %0, t; }" : "=r"(a) : "l"(p));
    return a;
}
__device__ __forceinline__ void ldm4(uint32_t* r, uint32_t addr) {
    asm volatile("ldmatrix.sync.aligned.m8n8.x4.shared.b16 {%0,%1,%2,%3}, [%4];"
        : "=r"(r[0]), "=r"(r[1]), "=r"(r[2]), "=r"(r[3]) : "r"(addr));
}
__device__ __forceinline__ void mma_bf16(float* d, const uint32_t* a, const uint32_t* b) {
    asm volatile("mma.sync.aligned.m16n8k16.row.col.f32.bf16.bf16.f32 "
        "{%0,%1,%2,%3}, {%4,%5,%6,%7}, {%8,%9}, {%0,%1,%2,%3};"
        : "+f"(d[0]), "+f"(d[1]), "+f"(d[2]), "+f"(d[3])
        : "r"(a[0]), "r"(a[1]), "r"(a[2]), "r"(a[3]), "r"(b[0]), "r"(b[1]));
}
__device__ __forceinline__ uint32_t pack_bf16(float a, float b) {
    __nv_bfloat162 p = __floats2bfloat162_rn(a, b);
    return *(uint32_t*)&p;
}
__device__ __forceinline__ void cpa16(uint32_t dst, const void* src) {
    asm volatile("cp.async.cg.shared.global [%0], [%1], 16;" :: "r"(dst), "l"(src) : "memory");
}
#define CP_COMMIT() asm volatile("cp.async.commit_group;" ::: "memory")
#define CP_WAIT(n)  asm volatile("cp.async.wait_group %0;" :: "n"(n) : "memory")

// ---------------- kNN ----------------
__global__ void knn_kernel(const float* __restrict__ xyz,
                           const float* __restrict__ xyzp) {
    __shared__ float4 sp[NP];
    int b = blockIdx.y;
    const float* p = xyzp + (size_t)b*3*NP;
    for (int j = threadIdx.x; j < NP; j += blockDim.x) {
        float X = p[j], Y = p[NP + j], Z = p[2*NP + j];
        sp[j] = make_float4(X, Y, Z, X*X + Y*Y + Z*Z);
    }
    __syncthreads();
    int n = blockIdx.x*blockDim.x + threadIdx.x;
    const float* q = xyz + (size_t)b*3*N0;
    float qx = q[n], qy = q[N0 + n], qz = q[2*N0 + n];
    float q2 = qx*qx + qy*qy + qz*qz;
    float d0 = 1e30f, d1 = 1e30f, d2 = 1e30f;
    int   i0 = 0, i1 = 0, i2 = 0;
#pragma unroll 4
    for (int j = 0; j < NP; ++j) {
        float4 v = sp[j];
        float dot = qx*v.x + qy*v.y + qz*v.z;
        float d = (q2 + v.w) - 2.0f*dot;
        if (d < d2) {
            if (d < d1) {
                d2 = d1; i2 = i1;
                if (d < d0) { d1 = d0; i1 = i0; d0 = d; i0 = j; }
                else        { d1 = d;  i1 = j; }
            } else { d2 = d; i2 = j; }
        }
    }
    float e0 = 1.0f/(fmaxf(d0, 1e-10f) + 1e-8f);
    float e1 = 1.0f/(fmaxf(d1, 1e-10f) + 1e-8f);
    float e2 = 1.0f/(fmaxf(d2, 1e-10f) + 1e-8f);
    float inv = 1.0f/(e0 + e1 + e2);
    size_t base = ((size_t)b*N0 + n)*3;
    g_idx[base]   = i0; g_idx[base+1] = i1; g_idx[base+2] = i2;
    g_wt [base]   = e0*inv; g_wt[base+1] = e1*inv; g_wt[base+2] = e2*inv;
}

// ---------------- transpose + (optional BN/LReLU) + bf16 hi/lo split ----------------
// src [b][C][N] fp32 -> hi/lo [b][N][C] bf16.  Tile: 64 C x 32 N.
__global__ void transconv_kernel(const float* __restrict__ src,
                                 __nv_bfloat16* __restrict__ hi,
                                 __nv_bfloat16* __restrict__ lo,
                                 int C, int N, int bn) {
    __shared__ float st[64][33];
    int b = blockIdx.z;
    int c0 = blockIdx.y*64, n0 = blockIdx.x*32;
    const float* s = src + (size_t)b*C*N;
    int t = threadIdx.x;
    for (int i = t; i < 64*32; i += 256) {
        int c = i >> 5, n = i & 31;
        float x = s[(size_t)(c0 + c)*N + n0 + n];
        if (bn) {
            x = fmaf(x, g_sc1[c0 + c], g_bi1[c0 + c]);
            x = (x >= 0.f) ? x : 0.01f*x;
        }
        st[c][n] = x;
    }
    __syncthreads();
    uint32_t* hp = (uint32_t*)(hi + (size_t)b*N*C);
    uint32_t* lp = (uint32_t*)(lo + (size_t)b*N*C);
    for (int i = t; i < 32*32; i += 256) {
        int n = i >> 5, p = i & 31;
        float x0 = st[2*p][n], x1 = st[2*p + 1][n];
        __nv_bfloat16 h0 = __float2bfloat16(x0), h1 = __float2bfloat16(x1);
        float l0 = x0 - __bfloat162float(h0);
        float l1 = x1 - __bfloat162float(h1);
        size_t ro = (((size_t)(n0 + n)*C + c0) >> 1) + p;
        hp[ro] = pack_bf16(x0, x1);
        lp[ro] = pack_bf16(l0, l1);
    }
}

// ---------------- weight convert (elementwise, no transpose) ----------------
__global__ void wconv_kernel(const float* __restrict__ w,
                             __nv_bfloat16* __restrict__ hi,
                             __nv_bfloat16* __restrict__ lo, int npairs) {
    int i = blockIdx.x*blockDim.x + threadIdx.x;
    if (i >= npairs) return;
    float x0 = w[2*i], x1 = w[2*i + 1];
    __nv_bfloat16 h0 = __float2bfloat16(x0), h1 = __float2bfloat16(x1);
    float l0 = x0 - __bfloat162float(h0);
    float l1 = x1 - __bfloat162float(h1);
    ((uint32_t*)hi)[i] = pack_bf16(x0, x1);
    ((uint32_t*)lo)[i] = pack_bf16(l0, l1);
}

// ===================== bf16x3 mma.sync GEMM core: cp.async, 2-stage =====================
// 512 threads, 16 warps (4 n x 4 o), CTA tile 128n x 128o, K chunk 64.
__device__ __forceinline__ void issue_chunk(uint32_t sbst,
    const __nv_bfloat16* Ahi, const __nv_bfloat16* Alo, int ldkA, size_t arow0, int kA,
    const __nv_bfloat16* Bhi, const __nv_bfloat16* Blo, int ldkB, size_t brow0, int kB,
    int rs, int q)
{
#pragma unroll
    for (int j = 0; j < 4; j++) {
        int seg = q*4 + j;                        // 0..15
        int ksub = (seg & 7) * 8;
        uint32_t doff = (seg < 8) ? seg*16 : 128 + (seg - 8)*16;
        const __nv_bfloat16* asrc = (seg < 8 ? Ahi : Alo) + arow0 + (size_t)rs*ldkA + kA + ksub;
        cpa16(sbst + O_AS + rs*PITCH + doff, asrc);
        const __nv_bfloat16* bsrc = (seg < 8 ? Bhi : Blo) + brow0 + (size_t)rs*ldkB + kB + ksub;
        cpa16(sbst + O_BS + rs*PITCH + doff, bsrc);
    }
}

__device__ __forceinline__ void gemm_core(uint32_t sb,
    const __nv_bfloat16* Ahi, const __nv_bfloat16* Alo, int ldkA, size_t arow0, int kA0,
    const __nv_bfloat16* Bhi, const __nv_bfloat16* Blo, int ldkB, size_t brow0, int kB0,
    int nk64, float acc[2][4][4])
{
    int t = threadIdx.x, lane = t & 31, wid = t >> 5;
    int wn = wid & 3, wo = wid >> 2;
    int rs = t & 127, q = t >> 7;
    uint32_t aAddr = sb + (uint32_t)(O_AS + (wn*32 + (lane & 15))*PITCH + ((lane >> 4) & 1)*16);
    uint32_t bAddr = sb + (uint32_t)(O_BS + (wo*32 + (lane & 7) + ((lane >> 4) & 1)*8)*PITCH
                                     + ((lane >> 3) & 1)*16);
    issue_chunk(sb, Ahi, Alo, ldkA, arow0, kA0, Bhi, Blo, ldkB, brow0, kB0, rs, q);
    CP_COMMIT();
    for (int it = 0; it < nk64; it++) {
        if (it + 1 < nk64) {
            issue_chunk(sb + ((it + 1) & 1)*STAGE,
                        Ahi, Alo, ldkA, arow0, kA0 + (it + 1)*64,
                        Bhi, Blo, ldkB, brow0, kB0 + (it + 1)*64, rs, q);
            CP_COMMIT();
            CP_WAIT(1);
        } else {
            CP_WAIT(0);
        }
        __syncthreads();
        uint32_t stO = (it & 1) ? (uint32_t)STAGE : 0u;
#pragma unroll
        for (int s16 = 0; s16 < 4; s16++) {
            uint32_t Ah[2][4], Al[2][4], Bh[2][4], Bl[2][4];
#pragma unroll
            for (int mt = 0; mt < 2; mt++) {
                uint32_t ad = aAddr + stO + mt*16*PITCH + s16*32;
                ldm4(Ah[mt], ad); ldm4(Al[mt], ad + 128);
            }
#pragma unroll
            for (int np = 0; np < 2; np++) {
                uint32_t bd = bAddr + stO + np*16*PITCH + s16*32;
                ldm4(Bh[np], bd); ldm4(Bl[np], bd + 128);
            }
#pragma unroll
            for (int mt = 0; mt < 2; mt++)
#pragma unroll
            for (int nt = 0; nt < 4; nt++) {
                const uint32_t* bh = &Bh[nt >> 1][(nt & 1)*2];
                const uint32_t* bl = &Bl[nt >> 1][(nt & 1)*2];
                mma_bf16(acc[mt][nt], Ah[mt], bh);
                mma_bf16(acc[mt][nt], Ah[mt], bl);
                mma_bf16(acc[mt][nt], Al[mt], bh);
            }
        }
        __syncthreads();
    }
}

// dump one 32-o strip of accumulators into sbuf[o_local][n]
__device__ __forceinline__ void dump_strip(float* sbuf, int s, float acc[2][4][4]) {
    int t = threadIdx.x, lane = t & 31, wid = t >> 5;
    int wn = wid & 3, wo = wid >> 2;
    if (wo != s) return;
    int g = lane >> 2, c2 = (lane & 3)*2;
#pragma unroll
    for (int mt = 0; mt < 2; mt++)
#pragma unroll
    for (int nt = 0; nt < 4; nt++) {
        int nl = wn*32 + mt*16 + g;
        int ol = nt*8 + c2;
        sbuf[ol*132 + nl]         = acc[mt][nt][0];
        sbuf[(ol+1)*132 + nl]     = acc[mt][nt][1];
        sbuf[ol*132 + nl + 8]     = acc[mt][nt][2];
        sbuf[(ol+1)*132 + nl + 8] = acc[mt][nt][3];
    }
}

// ---------- GEMM 1a: Gt[b][n][o] = W1[:, :512] @ feat ----------
__global__ __launch_bounds__(512, 1)
void gemm1a_kernel() {
    extern __shared__ __align__(16) char sm[];
    uint32_t sb = smem_u32(sm);
    int b = blockIdx.z, nb = blockIdx.x*128, ob = blockIdx.y*128;
    int t = threadIdx.x;
    float acc[2][4][4] = {};
    gemm_core(sb, g_fA_hi, g_fA_lo, CPf, (size_t)b*NP*CPf + (size_t)nb*CPf, 0,
                  g_W1_hi, g_W1_lo, KW,  (size_t)ob*KW, 0, CPf/64, acc);
    float* sbuf = (float*)(sm + O_SBUF);
    int n = t & 127, oq = t >> 7;
    for (int s = 0; s < 4; s++) {
        __syncthreads();
        dump_strip(sbuf, s, acc);
        __syncthreads();
        float f[8];
#pragma unroll
        for (int j = 0; j < 8; j++) f[j] = sbuf[(oq*8 + j)*132 + n];
        float* dst = &g_Gt[((size_t)b*NP + nb + n)*C1f + ob + s*32 + oq*8];
        *(float4*)dst       = make_float4(f[0], f[1], f[2], f[3]);
        *(float4*)(dst + 4) = make_float4(f[4], f[5], f[6], f[7]);
    }
}

// shared epilogue: optional gather, transpose writeout [o][n], BN-stat partials
__device__ __forceinline__ void epi_write(char* sm, float acc[2][4][4],
                                          float* __restrict__ Y, int nb, int ob,
                                          int b, bool gather) {
    int t = threadIdx.x;
    float* sbuf = (float*)(sm + O_SBUF);
    int*   sid  = (int*)(sm + O_SID);
    float* swt  = (float*)(sm + O_SWT);
    float* chs  = (float*)(sm + O_CHS);
    float* chq  = (float*)(sm + O_CHQ);
    if (gather) {
        for (int i = t; i < 384; i += 512) {
            size_t base = ((size_t)b*N0 + nb)*3 + i;
            sid[i] = g_idx[base]; swt[i] = g_wt[base];
        }
    }
    const float* Gt = g_Gt + (size_t)b*NP*C1f;
    for (int s = 0; s < 4; s++) {
        __syncthreads();
        dump_strip(sbuf, s, acc);
        __syncthreads();
        if (gather) {
            int n = t & 127, oq = t >> 7;
            float v[8];
#pragma unroll
            for (int j = 0; j < 8; j++) v[j] = sbuf[(oq*8 + j)*132 + n];
#pragma unroll
            for (int k = 0; k < 3; k++) {
                int   id = sid[n*3 + k];
                float wk = swt[n*3 + k];
                const float* gp = &Gt[(size_t)id*C1f + ob + s*32 + oq*8];
                float4 g0 = *(const float4*)gp;
                float4 g1 = *(const float4*)(gp + 4);
                v[0] = fmaf(wk, g0.x, v[0]); v[1] = fmaf(wk, g0.y, v[1]);
                v[2] = fmaf(wk, g0.z, v[2]); v[3] = fmaf(wk, g0.w, v[3]);
                v[4] = fmaf(wk, g1.x, v[4]); v[5] = fmaf(wk, g1.y, v[5]);
                v[6] = fmaf(wk, g1.z, v[6]); v[7] = fmaf(wk, g1.w, v[7]);
            }
#pragma unroll
            for (int j = 0; j < 8; j++) sbuf[(oq*8 + j)*132 + n] = v[j];
            __syncthreads();
        }
        {
            int ol = t >> 4, seg = t & 15, n = seg*8;
            const float* srow = &sbuf[ol*132 + n];
            float4 x0 = *(const float4*)srow;
            float4 x1 = *(const float4*)(srow + 4);
            float s1 = x0.x + x0.y + x0.z + x0.w + x1.x + x1.y + x1.z + x1.w;
            float s2 = 0.f;
            s2 = fmaf(x0.x, x0.x, s2); s2 = fmaf(x0.y, x0.y, s2);
            s2 = fmaf(x0.z, x0.z, s2); s2 = fmaf(x0.w, x0.w, s2);
            s2 = fmaf(x1.x, x1.x, s2); s2 = fmaf(x1.y, x1.y, s2);
            s2 = fmaf(x1.z, x1.z, s2); s2 = fmaf(x1.w, x1.w, s2);
            float* dst = &Y[(size_t)(ob + s*32 + ol)*N0 + nb + n];
            *(float4*)dst       = x0;
            *(float4*)(dst + 4) = x1;
#pragma unroll
            for (int off = 8; off; off >>= 1) {
                s1 += __shfl_down_sync(0xffffffffu, s1, off, 16);
                s2 += __shfl_down_sync(0xffffffffu, s2, off, 16);
            }
            if (seg == 0) { chs[s*32 + ol] = s1; chq[s*32 + ol] = s2; }
        }
    }
    __syncthreads();
    if (t < 128) {
        int pidx = blockIdx.x + 64*blockIdx.z;
        g_p1[(size_t)(ob + t)*512 + pidx] = chs[t];
        g_p2[(size_t)(ob + t)*512 + pidx] = chq[t];
    }
}

// ---- GEMM 1b: y1 = W1[:, 512:] @ skip + interp(Gt); fused stats ----
__global__ __launch_bounds__(512, 1)
void gemm1b_kernel() {
    extern __shared__ __align__(16) char sm[];
    uint32_t sb = smem_u32(sm);
    int b = blockIdx.z, nb = blockIdx.x*128, ob = blockIdx.y*128;
    float acc[2][4][4] = {};
    gemm_core(sb, g_fS_hi, g_fS_lo, CSf, (size_t)b*N0*CSf + (size_t)nb*CSf, 0,
                  g_W1_hi, g_W1_lo, KW,  (size_t)ob*KW, CPf, CSf/64, acc);
    epi_write(sm, acc, g_y1 + (size_t)b*C1f*N0, nb, ob, b, true);
}

// ---- GEMM 2: z = W2 @ lrelu(BN1(y1)) (BN pre-applied in transconv); fused stats ----
__global__ __launch_bounds__(512, 1)
void gemm2_kernel() {
    extern __shared__ __align__(16) char sm[];
    uint32_t sb = smem_u32(sm);
    int b = blockIdx.z, nb = blockIdx.x*128, ob = blockIdx.y*128;
    float acc[2][4][4] = {};
    gemm_core(sb, g_yb_hi, g_yb_lo, C1f, (size_t)b*N0*C1f + (size_t)nb*C1f, 0,
                  g_W2_hi, g_W2_lo, C1f, (size_t)ob*C1f, 0, C1f/64, acc);
    epi_write(sm, acc, g_z + (size_t)b*C2f*N0, nb, ob, b, false);
}

// ---------------- stats reduce ----------------
__global__ void stats_reduce(const float* __restrict__ gain,
                             const float* __restrict__ beta, int layer) {
    int o = blockIdx.x, t = threadIdx.x;
    const float* p1 = &g_p1[(size_t)o*512];
    const float* p2 = &g_p2[(size_t)o*512];
    float a = p1[t] + p1[t+128] + p1[t+256] + p1[t+384];
    float c = p2[t] + p2[t+128] + p2[t+256] + p2[t+384];
    __shared__ float r1[128], r2[128];
    r1[t] = a; r2[t] = c; __syncthreads();
    for (int h = 64; h > 0; h >>= 1) {
        if (t < h) { r1[t] += r1[t+h]; r2[t] += r2[t+h]; }
        __syncthreads();
    }
    if (t == 0) {
        const float invN = 1.0f/((float)BB*N0);
        float m   = r1[0]*invN;
        float var = r2[0]*invN - m*m;
        float sc  = gain[o] * (1.0f/sqrtf(var + 1e-3f));
        if (layer) { g_sc2[o] = sc; g_bi2[o] = beta[o] - m*sc; }
        else       { g_sc1[o] = sc; g_bi1[o] = beta[o] - m*sc; }
    }
}

// ---------------- output: lrelu(BN2(z)) ----------------
__global__ void out_kernel(float* __restrict__ out) {
    size_t i = (size_t)blockIdx.x*blockDim.x + threadIdx.x;
    const size_t total4 = (size_t)BB*C2f*N0/4;
    if (i >= total4) return;
    int ch = (int)((i/(N0/4)) % C2f);
    float sc = g_sc2[ch], bi = g_bi2[ch];
    float4 v = *((const float4*)g_z + i);
    v.x = fmaf(v.x, sc, bi); v.x = (v.x >= 0.f) ? v.x : 0.01f*v.x;
    v.y = fmaf(v.y, sc, bi); v.y = (v.y >= 0.f) ? v.y : 0.01f*v.y;
    v.z = fmaf(v.z, sc, bi); v.z = (v.z >= 0.f) ? v.z : 0.01f*v.z;
    v.w = fmaf(v.w, sc, bi); v.w = (v.w >= 0.f) ? v.w : 0.01f*v.w;
    *((float4*)out + i) = v;
}

// ---------------- launch ----------------
extern "C" void kernel_launch(void* const* d_in, const int* in_sizes, int n_in,
                              void* d_out, int out_size) {
    const float* xyz   = (const float*)d_in[0];
    const float* skip  = (const float*)d_in[1];
    const float* xyzp  = (const float*)d_in[2];
    const float* featp = (const float*)d_in[3];
    const float* W1    = (const float*)d_in[4];
    const float* g1    = (const float*)d_in[5];
    const float* b1    = (const float*)d_in[6];
    const float* W2    = (const float*)d_in[7];
    const float* g2    = (const float*)d_in[8];
    const float* b2    = (const float*)d_in[9];
    float* out = (float*)d_out;

    static int s_attr = 0;
    if (!s_attr) {
        cudaFuncSetAttribute(gemm1a_kernel, cudaFuncAttributeMaxDynamicSharedMemorySize, SM_BYTES);
        cudaFuncSetAttribute(gemm1b_kernel, cudaFuncAttributeMaxDynamicSharedMemorySize, SM_BYTES);
        cudaFuncSetAttribute(gemm2_kernel,  cudaFuncAttributeMaxDynamicSharedMemorySize, SM_BYTES);
        s_attr = 1;
    }

    __nv_bfloat16 *fa_hi, *fa_lo, *fs_hi, *fs_lo, *yb_hi, *yb_lo;
    __nv_bfloat16 *w1_hi, *w1_lo, *w2_hi, *w2_lo;
    cudaGetSymbolAddress((void**)&fa_hi, g_fA_hi); cudaGetSymbolAddress((void**)&fa_lo, g_fA_lo);
    cudaGetSymbolAddress((void**)&fs_hi, g_fS_hi); cudaGetSymbolAddress((void**)&fs_lo, g_fS_lo);
    cudaGetSymbolAddress((void**)&yb_hi, g_yb_hi); cudaGetSymbolAddress((void**)&yb_lo, g_yb_lo);
    cudaGetSymbolAddress((void**)&w1_hi, g_W1_hi); cudaGetSymbolAddress((void**)&w1_lo, g_W1_lo);
    cudaGetSymbolAddress((void**)&w2_hi, g_W2_hi); cudaGetSymbolAddress((void**)&w2_lo, g_W2_lo);
    float* y1p; cudaGetSymbolAddress((void**)&y1p, g_y1);

    const size_t xyz_elems = (size_t)BB*3*N0;
    const size_t nf_elems  = (size_t)BB*C2f*N0;
    size_t off = 0;
    if ((size_t)out_size >= xyz_elems + nf_elems) {
        cudaMemcpyAsync(out, xyz, xyz_elems*sizeof(float), cudaMemcpyDeviceToDevice);
        off = xyz_elems;
    }

    knn_kernel      <<<dim3(N0/256, BB), 256>>>(xyz, xyzp);
    wconv_kernel    <<<(C1f*KW/2 + 255)/256,  256>>>(W1, w1_hi, w1_lo, C1f*KW/2);
    wconv_kernel    <<<(C2f*C1f/2 + 255)/256, 256>>>(W2, w2_hi, w2_lo, C2f*C1f/2);
    transconv_kernel<<<dim3(NP/32, CPf/64, BB), 256>>>(featp, fa_hi, fa_lo, CPf, NP, 0);
    transconv_kernel<<<dim3(N0/32, CSf/64, BB), 256>>>(skip,  fs_hi, fs_lo, CSf, N0, 0);
    gemm1a_kernel   <<<dim3(NP/128, C1f/128, BB), 512, SM_BYTES>>>();
    gemm1b_kernel   <<<dim3(N0/128, C1f/128, BB), 512, SM_BYTES>>>();
    stats_reduce    <<<C1f, 128>>>(g1, b1, 0);
    transconv_kernel<<<dim3(N0/32, C1f/64, BB), 256>>>(y1p, yb_hi, yb_lo, C1f, N0, 1);
    gemm2_kernel    <<<dim3(N0/128, C2f/128, BB), 512, SM_BYTES>>>();
    stats_reduce    <<<C2f, 128>>>(g2, b2, 1);
    out_kernel      <<<(unsigned)((nf_elems/4 + 255)/256), 256>>>(out + off);
}

// round 7
// speedup vs baseline: 1.2826x; 1.2826x over previous
#include <cuda_runtime.h>
#include <cuda_bf16.h>
#include <cstdint>

#define BB  8
#define N0  8192
#define NP  2048
#define CPf 512
#define CSf 256
#define C1f 256
#define C2f 256
#define KW  768   // CP+CS

// smem row: 64 bf16 hi (128B) | 64 bf16 lo (128B) | pad 16B
#define PITCH 272
#define ASZ   34816              // 128 * PITCH
#define O_AS  0
#define O_B0  34816
#define O_B1  69632
#define SM_BYTES 104448
// epilogue overlays (inside A tile region, used after mainloop)
#define O_SBUF 0                 // 32 x 132 floats
#define O_SID  16896
#define O_SWT  18432
#define O_CHS  19968
#define O_CHQ  20480

// ---------------- scratch (device globals) ----------------
__device__ int   g_idx[BB*N0*3];
__device__ float g_wt [BB*N0*3];
__device__ float g_Gt [BB*NP*C1f];
__device__ float g_y1 [BB*C1f*N0];
__device__ float g_z  [BB*C2f*N0];
__device__ float g_p1 [C1f*512], g_p2[C1f*512];
__device__ float g_sc1[C1f], g_bi1[C1f], g_sc2[C2f], g_bi2[C2f];
// pre-converted weights (hi/lo bf16, row-major [o][k])
__device__ __align__(16) __nv_bfloat16 g_W1_hi[C1f*KW],  g_W1_lo[C1f*KW];
__device__ __align__(16) __nv_bfloat16 g_W2_hi[C2f*C1f], g_W2_lo[C2f*C1f];

// ---------------- PTX wrappers (baseline ISA, compute_103-safe) ----------------
__device__ __forceinline__ uint32_t smem_u32(const void* p) {
    uint32_t a;
    asm("{ .reg .u64 t; cvta.to.shared.u64 t, %1; cvt.u32.u64 %0, t; }" : "=r"(a) : "l"(p));
    return a;
}
__device__ __forceinline__ void ldm4(uint32_t* r, uint32_t addr) {
    asm volatile("ldmatrix.sync.aligned.m8n8.x4.shared.b16 {%0,%1,%2,%3}, [%4];"
        : "=r"(r[0]), "=r"(r[1]), "=r"(r[2]), "=r"(r[3]) : "r"(addr));
}
__device__ __forceinline__ void mma_bf16(float* d, const uint32_t* a, const uint32_t* b) {
    asm volatile("mma.sync.aligned.m16n8k16.row.col.f32.bf16.bf16.f32 "
        "{%0,%1,%2,%3}, {%4,%5,%6,%7}, {%8,%9}, {%0,%1,%2,%3};"
        : "+f"(d[0]), "+f"(d[1]), "+f"(d[2]), "+f"(d[3])
        : "r"(a[0]), "r"(a[1]), "r"(a[2]), "r"(a[3]), "r"(b[0]), "r"(b[1]));
}
__device__ __forceinline__ uint32_t pack_bf16(float a, float b) {
    __nv_bfloat162 p = __floats2bfloat162_rn(a, b);
    return *(uint32_t*)&p;
}
__device__ __forceinline__ void cpa16(uint32_t dst, const void* src) {
    asm volatile("cp.async.cg.shared.global [%0], [%1], 16;" :: "r"(dst), "l"(src) : "memory");
}
#define CP_COMMIT() asm volatile("cp.async.commit_group;" ::: "memory")
#define CP_WAIT(n)  asm volatile("cp.async.wait_group %0;" :: "n"(n) : "memory")

// ---------------- kNN ----------------
__global__ void knn_kernel(const float* __restrict__ xyz,
                           const float* __restrict__ xyzp) {
    __shared__ float4 sp[NP];
    int b = blockIdx.y;
    const float* p = xyzp + (size_t)b*3*NP;
    for (int j = threadIdx.x; j < NP; j += blockDim.x) {
        float X = p[j], Y = p[NP + j], Z = p[2*NP + j];
        sp[j] = make_float4(X, Y, Z, X*X + Y*Y + Z*Z);
    }
    __syncthreads();
    int n = blockIdx.x*blockDim.x + threadIdx.x;
    const float* q = xyz + (size_t)b*3*N0;
    float qx = q[n], qy = q[N0 + n], qz = q[2*N0 + n];
    float q2 = qx*qx + qy*qy + qz*qz;
    float d0 = 1e30f, d1 = 1e30f, d2 = 1e30f;
    int   i0 = 0, i1 = 0, i2 = 0;
#pragma unroll 4
    for (int j = 0; j < NP; ++j) {
        float4 v = sp[j];
        float dot = qx*v.x + qy*v.y + qz*v.z;
        float d = (q2 + v.w) - 2.0f*dot;
        if (d < d2) {
            if (d < d1) {
                d2 = d1; i2 = i1;
                if (d < d0) { d1 = d0; i1 = i0; d0 = d; i0 = j; }
                else        { d1 = d;  i1 = j; }
            } else { d2 = d; i2 = j; }
        }
    }
    float e0 = 1.0f/(fmaxf(d0, 1e-10f) + 1e-8f);
    float e1 = 1.0f/(fmaxf(d1, 1e-10f) + 1e-8f);
    float e2 = 1.0f/(fmaxf(d2, 1e-10f) + 1e-8f);
    float inv = 1.0f/(e0 + e1 + e2);
    size_t base = ((size_t)b*N0 + n)*3;
    g_idx[base]   = i0; g_idx[base+1] = i1; g_idx[base+2] = i2;
    g_wt [base]   = e0*inv; g_wt[base+1] = e1*inv; g_wt[base+2] = e2*inv;
}

// ---------------- weight convert (elementwise) ----------------
__global__ void wconv_kernel(const float* __restrict__ w,
                             __nv_bfloat16* __restrict__ hi,
                             __nv_bfloat16* __restrict__ lo, int npairs) {
    int i = blockIdx.x*blockDim.x + threadIdx.x;
    if (i >= npairs) return;
    float x0 = w[2*i], x1 = w[2*i + 1];
    __nv_bfloat16 h0 = __float2bfloat16(x0), h1 = __float2bfloat16(x1);
    float l0 = x0 - __bfloat162float(h0);
    float l1 = x1 - __bfloat162float(h1);
    ((uint32_t*)hi)[i] = pack_bf16(x0, x1);
    ((uint32_t*)lo)[i] = pack_bf16(l0, l1);
}

// ===================== bf16x3 mma.sync GEMM core =====================
// 512 threads, 16 warps (4 n x 4 o), CTA tile 128n x 128o, K chunk 64.
// A: fp32 in-loop convert (reg prefetch). B: pre-converted bf16 via 2-stage cp.async.

__device__ __forceinline__ void issue_B(uint32_t dstbase,
    const __nv_bfloat16* __restrict__ Whi, const __nv_bfloat16* __restrict__ Wlo,
    int ldw, int ob, int k0, int rs, int q)
{
#pragma unroll
    for (int j = 0; j < 4; j++) {
        int seg = q*4 + j;                         // 0..15: 0-7 hi, 8-15 lo
        uint32_t doff = (seg < 8) ? (uint32_t)(seg*16) : (uint32_t)(128 + (seg - 8)*16);
        const __nv_bfloat16* src = ((seg < 8) ? Whi : Wlo)
                                   + (size_t)(ob + rs)*ldw + k0 + (seg & 7)*8;
        cpa16(dstbase + rs*PITCH + doff, src);
    }
}

template<bool BN>
__device__ __forceinline__ void gemm_core(char* sm, uint32_t sb,
    const float* __restrict__ A, int ldn, int nb, int kA0,
    const __nv_bfloat16* __restrict__ Whi, const __nv_bfloat16* __restrict__ Wlo,
    int ldw, int ob, int kW0, int nk64, float acc[2][4][4])
{
    int t = threadIdx.x, lane = t & 31, wid = t >> 5;
    int wn = wid & 3, wo = wid >> 2;
    int rs = t & 127, q = t >> 7;
    uint32_t aAddr = sb + (uint32_t)(O_AS + (wn*32 + (lane & 15))*PITCH + ((lane >> 4) & 1)*16);
    uint32_t bOff  = (uint32_t)((wo*32 + (lane & 7) + ((lane >> 4) & 1)*8)*PITCH
                                + ((lane >> 3) & 1)*16);
    uint32_t bBase0 = sb + O_B0, bBase1 = sb + O_B1;
    float ax[16];
    // prologue: B(0) cp.async + A(0) register prefetch
    issue_B(bBase0, Whi, Wlo, ldw, ob, kW0, rs, q);
    CP_COMMIT();
    {
        const float* ap = A + (size_t)(kA0 + q*16)*ldn + nb + rs;
#pragma unroll
        for (int j = 0; j < 16; j++) ax[j] = ap[(size_t)j*ldn];
    }
    for (int it = 0; it < nk64; it++) {
        // ---- convert + STS A(cur) ----
        {
            int kA = it*64 + q*16;
            float x[16];
#pragma unroll
            for (int j = 0; j < 16; j++) x[j] = ax[j];
            if (BN) {
#pragma unroll
                for (int j = 0; j < 16; j++) {
                    float v = fmaf(x[j], g_sc1[kA + j], g_bi1[kA + j]);
                    x[j] = (v >= 0.f) ? v : 0.01f*v;
                }
            }
            float lo[16];
#pragma unroll
            for (int j = 0; j < 16; j++) {
                __nv_bfloat16 h = __float2bfloat16(x[j]);
                lo[j] = x[j] - __bfloat162float(h);
            }
            char* arow = sm + O_AS + rs*PITCH + q*32;
            *(uint4*)arow = make_uint4(pack_bf16(x[0], x[1]),  pack_bf16(x[2], x[3]),
                                       pack_bf16(x[4], x[5]),  pack_bf16(x[6], x[7]));
            *(uint4*)(arow + 16) = make_uint4(pack_bf16(x[8], x[9]),   pack_bf16(x[10], x[11]),
                                              pack_bf16(x[12], x[13]), pack_bf16(x[14], x[15]));
            *(uint4*)(arow + 128) = make_uint4(pack_bf16(lo[0], lo[1]), pack_bf16(lo[2], lo[3]),
                                               pack_bf16(lo[4], lo[5]), pack_bf16(lo[6], lo[7]));
            *(uint4*)(arow + 144) = make_uint4(pack_bf16(lo[8], lo[9]),   pack_bf16(lo[10], lo[11]),
                                               pack_bf16(lo[12], lo[13]), pack_bf16(lo[14], lo[15]));
        }
        // ---- B(it+1) cp.async into other stage; wait for B(cur) ----
        if (it + 1 < nk64) {
            issue_B(((it + 1) & 1) ? bBase1 : bBase0, Whi, Wlo, ldw, ob,
                    kW0 + (it + 1)*64, rs, q);
            CP_COMMIT();
            CP_WAIT(1);
        } else {
            CP_WAIT(0);
        }
        __syncthreads();
        // ---- A(it+1) register prefetch (overlaps MMAs below) ----
        if (it + 1 < nk64) {
            const float* ap = A + (size_t)(kA0 + (it + 1)*64 + q*16)*ldn + nb + rs;
#pragma unroll
            for (int j = 0; j < 16; j++) ax[j] = ap[(size_t)j*ldn];
        }
        // ---- compute: 4 k16 steps ----
        uint32_t bAddr = ((it & 1) ? bBase1 : bBase0) + bOff;
#pragma unroll
        for (int s16 = 0; s16 < 4; s16++) {
            uint32_t Ah[2][4], Al[2][4], Bh[2][4], Bl[2][4];
#pragma unroll
            for (int mt = 0; mt < 2; mt++) {
                uint32_t ad = aAddr + mt*16*PITCH + s16*32;
                ldm4(Ah[mt], ad); ldm4(Al[mt], ad + 128);
            }
#pragma unroll
            for (int np = 0; np < 2; np++) {
                uint32_t bd = bAddr + np*16*PITCH + s16*32;
                ldm4(Bh[np], bd); ldm4(Bl[np], bd + 128);
            }
#pragma unroll
            for (int mt = 0; mt < 2; mt++)
#pragma unroll
            for (int nt = 0; nt < 4; nt++) {
                const uint32_t* bh = &Bh[nt >> 1][(nt & 1)*2];
                const uint32_t* bl = &Bl[nt >> 1][(nt & 1)*2];
                mma_bf16(acc[mt][nt], Ah[mt], bh);
                mma_bf16(acc[mt][nt], Ah[mt], bl);
                mma_bf16(acc[mt][nt], Al[mt], bh);
            }
        }
        __syncthreads();
    }
}

// dump one 32-o strip of accumulators into sbuf[o_local][n]
__device__ __forceinline__ void dump_strip(float* sbuf, int s, float acc[2][4][4]) {
    int t = threadIdx.x, lane = t & 31, wid = t >> 5;
    int wn = wid & 3, wo = wid >> 2;
    if (wo != s) return;
    int g = lane >> 2, c2 = (lane & 3)*2;
#pragma unroll
    for (int mt = 0; mt < 2; mt++)
#pragma unroll
    for (int nt = 0; nt < 4; nt++) {
        int nl = wn*32 + mt*16 + g;
        int ol = nt*8 + c2;
        sbuf[ol*132 + nl]         = acc[mt][nt][0];
        sbuf[(ol+1)*132 + nl]     = acc[mt][nt][1];
        sbuf[ol*132 + nl + 8]     = acc[mt][nt][2];
        sbuf[(ol+1)*132 + nl + 8] = acc[mt][nt][3];
    }
}

// ---------- GEMM 1a: Gt[b][n][o] = W1[:, :512] @ feat ----------
__global__ __launch_bounds__(512, 1)
void gemm1a_kernel(const float* __restrict__ feat) {
    extern __shared__ __align__(16) char sm[];
    uint32_t sb = smem_u32(sm);
    int b = blockIdx.z, nb = blockIdx.x*128, ob = blockIdx.y*128;
    int t = threadIdx.x;
    float acc[2][4][4] = {};
    gemm_core<false>(sm, sb, feat + (size_t)b*CPf*NP, NP, nb, 0,
                     g_W1_hi, g_W1_lo, KW, ob, 0, CPf/64, acc);
    float* sbuf = (float*)(sm + O_SBUF);
    int n = t & 127, oq = t >> 7;
    for (int s = 0; s < 4; s++) {
        __syncthreads();
        dump_strip(sbuf, s, acc);
        __syncthreads();
        float f[8];
#pragma unroll
        for (int j = 0; j < 8; j++) f[j] = sbuf[(oq*8 + j)*132 + n];
        float* dst = &g_Gt[((size_t)b*NP + nb + n)*C1f + ob + s*32 + oq*8];
        *(float4*)dst       = make_float4(f[0], f[1], f[2], f[3]);
        *(float4*)(dst + 4) = make_float4(f[4], f[5], f[6], f[7]);
    }
}

// shared epilogue: optional gather, transpose writeout [o][n], BN-stat partials
__device__ __forceinline__ void epi_write(char* sm, float acc[2][4][4],
                                          float* __restrict__ Y, int nb, int ob,
                                          int b, bool gather) {
    int t = threadIdx.x;
    float* sbuf = (float*)(sm + O_SBUF);
    int*   sid  = (int*)(sm + O_SID);
    float* swt  = (float*)(sm + O_SWT);
    float* chs  = (float*)(sm + O_CHS);
    float* chq  = (float*)(sm + O_CHQ);
    if (gather) {
        for (int i = t; i < 384; i += 512) {
            size_t base = ((size_t)b*N0 + nb)*3 + i;
            sid[i] = g_idx[base]; swt[i] = g_wt[base];
        }
    }
    const float* Gt = g_Gt + (size_t)b*NP*C1f;
    for (int s = 0; s < 4; s++) {
        __syncthreads();
        dump_strip(sbuf, s, acc);
        __syncthreads();
        if (gather) {
            int n = t & 127, oq = t >> 7;
            float v[8];
#pragma unroll
            for (int j = 0; j < 8; j++) v[j] = sbuf[(oq*8 + j)*132 + n];
#pragma unroll
            for (int k = 0; k < 3; k++) {
                int   id = sid[n*3 + k];
                float wk = swt[n*3 + k];
                const float* gp = &Gt[(size_t)id*C1f + ob + s*32 + oq*8];
                float4 g0 = *(const float4*)gp;
                float4 g1 = *(const float4*)(gp + 4);
                v[0] = fmaf(wk, g0.x, v[0]); v[1] = fmaf(wk, g0.y, v[1]);
                v[2] = fmaf(wk, g0.z, v[2]); v[3] = fmaf(wk, g0.w, v[3]);
                v[4] = fmaf(wk, g1.x, v[4]); v[5] = fmaf(wk, g1.y, v[5]);
                v[6] = fmaf(wk, g1.z, v[6]); v[7] = fmaf(wk, g1.w, v[7]);
            }
#pragma unroll
            for (int j = 0; j < 8; j++) sbuf[(oq*8 + j)*132 + n] = v[j];
            __syncthreads();
        }
        {
            int ol = t >> 4, seg = t & 15, n = seg*8;
            const float* srow = &sbuf[ol*132 + n];
            float4 x0 = *(const float4*)srow;
            float4 x1 = *(const float4*)(srow + 4);
            float s1 = x0.x + x0.y + x0.z + x0.w + x1.x + x1.y + x1.z + x1.w;
            float s2 = 0.f;
            s2 = fmaf(x0.x, x0.x, s2); s2 = fmaf(x0.y, x0.y, s2);
            s2 = fmaf(x0.z, x0.z, s2); s2 = fmaf(x0.w, x0.w, s2);
            s2 = fmaf(x1.x, x1.x, s2); s2 = fmaf(x1.y, x1.y, s2);
            s2 = fmaf(x1.z, x1.z, s2); s2 = fmaf(x1.w, x1.w, s2);
            float* dst = &Y[(size_t)(ob + s*32 + ol)*N0 + nb + n];
            *(float4*)dst       = x0;
            *(float4*)(dst + 4) = x1;
#pragma unroll
            for (int off = 8; off; off >>= 1) {
                s1 += __shfl_down_sync(0xffffffffu, s1, off, 16);
                s2 += __shfl_down_sync(0xffffffffu, s2, off, 16);
            }
            if (seg == 0) { chs[s*32 + ol] = s1; chq[s*32 + ol] = s2; }
        }
    }
    __syncthreads();
    if (t < 128) {
        int pidx = blockIdx.x + 64*blockIdx.z;
        g_p1[(size_t)(ob + t)*512 + pidx] = chs[t];
        g_p2[(size_t)(ob + t)*512 + pidx] = chq[t];
    }
}

// ---- GEMM 1b: y1 = W1[:, 512:] @ skip + interp(Gt); fused stats ----
__global__ __launch_bounds__(512, 1)
void gemm1b_kernel(const float* __restrict__ skip) {
    extern __shared__ __align__(16) char sm[];
    uint32_t sb = smem_u32(sm);
    int b = blockIdx.z, nb = blockIdx.x*128, ob = blockIdx.y*128;
    float acc[2][4][4] = {};
    gemm_core<false>(sm, sb, skip + (size_t)b*CSf*N0, N0, nb, 0,
                     g_W1_hi, g_W1_lo, KW, ob, CPf, CSf/64, acc);
    epi_write(sm, acc, g_y1 + (size_t)b*C1f*N0, nb, ob, b, true);
}

// ---- GEMM 2: z = W2 @ lrelu(BN1(y1)); BN on A-stage; fused stats ----
__global__ __launch_bounds__(512, 1)
void gemm2_kernel() {
    extern __shared__ __align__(16) char sm[];
    uint32_t sb = smem_u32(sm);
    int b = blockIdx.z, nb = blockIdx.x*128, ob = blockIdx.y*128;
    float acc[2][4][4] = {};
    gemm_core<true>(sm, sb, g_y1 + (size_t)b*C1f*N0, N0, nb, 0,
                    g_W2_hi, g_W2_lo, C1f, ob, 0, C1f/64, acc);
    epi_write(sm, acc, g_z + (size_t)b*C2f*N0, nb, ob, b, false);
}

// ---------------- stats reduce ----------------
__global__ void stats_reduce(const float* __restrict__ gain,
                             const float* __restrict__ beta, int layer) {
    int o = blockIdx.x, t = threadIdx.x;
    const float* p1 = &g_p1[(size_t)o*512];
    const float* p2 = &g_p2[(size_t)o*512];
    float a = p1[t] + p1[t+128] + p1[t+256] + p1[t+384];
    float c = p2[t] + p2[t+128] + p2[t+256] + p2[t+384];
    __shared__ float r1[128], r2[128];
    r1[t] = a; r2[t] = c; __syncthreads();
    for (int h = 64; h > 0; h >>= 1) {
        if (t < h) { r1[t] += r1[t+h]; r2[t] += r2[t+h]; }
        __syncthreads();
    }
    if (t == 0) {
        const float invN = 1.0f/((float)BB*N0);
        float m   = r1[0]*invN;
        float var = r2[0]*invN - m*m;
        float sc  = gain[o] * (1.0f/sqrtf(var + 1e-3f));
        if (layer) { g_sc2[o] = sc; g_bi2[o] = beta[o] - m*sc; }
        else       { g_sc1[o] = sc; g_bi1[o] = beta[o] - m*sc; }
    }
}

// ---------------- output: lrelu(BN2(z)) ----------------
__global__ void out_kernel(float* __restrict__ out) {
    size_t i = (size_t)blockIdx.x*blockDim.x + threadIdx.x;
    const size_t total4 = (size_t)BB*C2f*N0/4;
    if (i >= total4) return;
    int ch = (int)((i/(N0/4)) % C2f);
    float sc = g_sc2[ch], bi = g_bi2[ch];
    float4 v = *((const float4*)g_z + i);
    v.x = fmaf(v.x, sc, bi); v.x = (v.x >= 0.f) ? v.x : 0.01f*v.x;
    v.y = fmaf(v.y, sc, bi); v.y = (v.y >= 0.f) ? v.y : 0.01f*v.y;
    v.z = fmaf(v.z, sc, bi); v.z = (v.z >= 0.f) ? v.z : 0.01f*v.z;
    v.w = fmaf(v.w, sc, bi); v.w = (v.w >= 0.f) ? v.w : 0.01f*v.w;
    *((float4*)out + i) = v;
}

// ---------------- launch ----------------
extern "C" void kernel_launch(void* const* d_in, const int* in_sizes, int n_in,
                              void* d_out, int out_size) {
    const float* xyz   = (const float*)d_in[0];
    const float* skip  = (const float*)d_in[1];
    const float* xyzp  = (const float*)d_in[2];
    const float* featp = (const float*)d_in[3];
    const float* W1    = (const float*)d_in[4];
    const float* g1    = (const float*)d_in[5];
    const float* b1    = (const float*)d_in[6];
    const float* W2    = (const float*)d_in[7];
    const float* g2    = (const float*)d_in[8];
    const float* b2    = (const float*)d_in[9];
    float* out = (float*)d_out;

    static int s_attr = 0;
    if (!s_attr) {
        cudaFuncSetAttribute(gemm1a_kernel, cudaFuncAttributeMaxDynamicSharedMemorySize, SM_BYTES);
        cudaFuncSetAttribute(gemm1b_kernel, cudaFuncAttributeMaxDynamicSharedMemorySize, SM_BYTES);
        cudaFuncSetAttribute(gemm2_kernel,  cudaFuncAttributeMaxDynamicSharedMemorySize, SM_BYTES);
        s_attr = 1;
    }

    __nv_bfloat16 *w1_hi, *w1_lo, *w2_hi, *w2_lo;
    cudaGetSymbolAddress((void**)&w1_hi, g_W1_hi); cudaGetSymbolAddress((void**)&w1_lo, g_W1_lo);
    cudaGetSymbolAddress((void**)&w2_hi, g_W2_hi); cudaGetSymbolAddress((void**)&w2_lo, g_W2_lo);

    const size_t xyz_elems = (size_t)BB*3*N0;
    const size_t nf_elems  = (size_t)BB*C2f*N0;
    size_t off = 0;
    if ((size_t)out_size >= xyz_elems + nf_elems) {
        cudaMemcpyAsync(out, xyz, xyz_elems*sizeof(float), cudaMemcpyDeviceToDevice);
        off = xyz_elems;
    }

    knn_kernel   <<<dim3(N0/256, BB), 256>>>(xyz, xyzp);
    wconv_kernel <<<(C1f*KW/2 + 255)/256,  256>>>(W1, w1_hi, w1_lo, C1f*KW/2);
    wconv_kernel <<<(C2f*C1f/2 + 255)/256, 256>>>(W2, w2_hi, w2_lo, C2f*C1f/2);
    gemm1a_kernel<<<dim3(NP/128, C1f/128, BB), 512, SM_BYTES>>>(featp);
    gemm1b_kernel<<<dim3(N0/128, C1f/128, BB), 512, SM_BYTES>>>(skip);
    stats_reduce <<<C1f, 128>>>(g1, b1, 0);
    gemm2_kernel <<<dim3(N0/128, C2f/128, BB), 512, SM_BYTES>>>();
    stats_reduce <<<C2f, 128>>>(g2, b2, 1);
    out_kernel   <<<(unsigned)((nf_elems/4 + 255)/256), 256>>>(out + off);
}

// round 8
// speedup vs baseline: 1.3305x; 1.0373x over previous
#include <cuda_runtime.h>
#include <cuda_bf16.h>
#include <cstdint>

#define BB  8
#define N0  8192
#define NP  2048
#define CPf 512
#define CSf 256
#define C1f 256
#define C2f 256
#define KW  768   // CP+CS

// smem row: 64 bf16 hi (128B) | 64 bf16 lo (128B) | pad 16B
#define PITCH 272
#define TSZ   34816              // 128 * PITCH
#define O_A0  0
#define O_A1  34816
#define O_B0  69632
#define O_B1  104448
#define SM_BYTES 139264
// epilogue overlays (inside A0 region, used after mainloop)
#define O_SBUF 0                 // 32 x 132 floats
#define O_SID  16896
#define O_SWT  18432
#define O_CHS  19968
#define O_CHQ  20480

// ---------------- scratch (device globals) ----------------
__device__ int   g_idx[BB*N0*3];
__device__ float g_wt [BB*N0*3];
__device__ float g_Gt [BB*NP*C1f];
__device__ float g_y1 [BB*C1f*N0];
__device__ float g_z  [BB*C2f*N0];
__device__ float g_p1 [C1f*512], g_p2[C1f*512];
__device__ float g_sc1[C1f], g_bi1[C1f], g_sc2[C2f], g_bi2[C2f];
// pre-converted weights (hi/lo bf16, row-major [o][k])
__device__ __align__(16) __nv_bfloat16 g_W1_hi[C1f*KW],  g_W1_lo[C1f*KW];
__device__ __align__(16) __nv_bfloat16 g_W2_hi[C2f*C1f], g_W2_lo[C2f*C1f];

// ---------------- PTX wrappers (baseline ISA, compute_103-safe) ----------------
__device__ __forceinline__ uint32_t smem_u32(const void* p) {
    uint32_t a;
    asm("{ .reg .u64 t; cvta.to.shared.u64 t, %1; cvt.u32.u64 %0, t; }" : "=r"(a) : "l"(p));
    return a;
}
__device__ __forceinline__ void ldm4(uint32_t* r, uint32_t addr) {
    asm volatile("ldmatrix.sync.aligned.m8n8.x4.shared.b16 {%0,%1,%2,%3}, [%4];"
        : "=r"(r[0]), "=r"(r[1]), "=r"(r[2]), "=r"(r[3]) : "r"(addr));
}
__device__ __forceinline__ void mma_bf16(float* d, const uint32_t* a, const uint32_t* b) {
    asm volatile("mma.sync.aligned.m16n8k16.row.col.f32.bf16.bf16.f32 "
        "{%0,%1,%2,%3}, {%4,%5,%6,%7}, {%8,%9}, {%0,%1,%2,%3};"
        : "+f"(d[0]), "+f"(d[1]), "+f"(d[2]), "+f"(d[3])
        : "r"(a[0]), "r"(a[1]), "r"(a[2]), "r"(a[3]), "r"(b[0]), "r"(b[1]));
}
__device__ __forceinline__ uint32_t pack_bf16(float a, float b) {
    __nv_bfloat162 p = __floats2bfloat162_rn(a, b);
    return *(uint32_t*)&p;
}
__device__ __forceinline__ void cpa16(uint32_t dst, const void* src) {
    asm volatile("cp.async.cg.shared.global [%0], [%1], 16;" :: "r"(dst), "l"(src) : "memory");
}
#define CP_COMMIT() asm volatile("cp.async.commit_group;" ::: "memory")
#define CP_WAIT(n)  asm volatile("cp.async.wait_group %0;" :: "n"(n) : "memory")

// ---------------- kNN ----------------
__global__ void knn_kernel(const float* __restrict__ xyz,
                           const float* __restrict__ xyzp) {
    __shared__ float4 sp[NP];
    int b = blockIdx.y;
    const float* p = xyzp + (size_t)b*3*NP;
    for (int j = threadIdx.x; j < NP; j += blockDim.x) {
        float X = p[j], Y = p[NP + j], Z = p[2*NP + j];
        sp[j] = make_float4(X, Y, Z, X*X + Y*Y + Z*Z);
    }
    __syncthreads();
    int n = blockIdx.x*blockDim.x + threadIdx.x;
    const float* q = xyz + (size_t)b*3*N0;
    float qx = q[n], qy = q[N0 + n], qz = q[2*N0 + n];
    float q2 = qx*qx + qy*qy + qz*qz;
    float d0 = 1e30f, d1 = 1e30f, d2 = 1e30f;
    int   i0 = 0, i1 = 0, i2 = 0;
#pragma unroll 4
    for (int j = 0; j < NP; ++j) {
        float4 v = sp[j];
        float dot = qx*v.x + qy*v.y + qz*v.z;
        float d = (q2 + v.w) - 2.0f*dot;
        if (d < d2) {
            if (d < d1) {
                d2 = d1; i2 = i1;
                if (d < d0) { d1 = d0; i1 = i0; d0 = d; i0 = j; }
                else        { d1 = d;  i1 = j; }
            } else { d2 = d; i2 = j; }
        }
    }
    float e0 = 1.0f/(fmaxf(d0, 1e-10f) + 1e-8f);
    float e1 = 1.0f/(fmaxf(d1, 1e-10f) + 1e-8f);
    float e2 = 1.0f/(fmaxf(d2, 1e-10f) + 1e-8f);
    float inv = 1.0f/(e0 + e1 + e2);
    size_t base = ((size_t)b*N0 + n)*3;
    g_idx[base]   = i0; g_idx[base+1] = i1; g_idx[base+2] = i2;
    g_wt [base]   = e0*inv; g_wt[base+1] = e1*inv; g_wt[base+2] = e2*inv;
}

// ---------------- weight convert (elementwise) ----------------
__global__ void wconv_kernel(const float* __restrict__ w,
                             __nv_bfloat16* __restrict__ hi,
                             __nv_bfloat16* __restrict__ lo, int npairs) {
    int i = blockIdx.x*blockDim.x + threadIdx.x;
    if (i >= npairs) return;
    float x0 = w[2*i], x1 = w[2*i + 1];
    __nv_bfloat16 h0 = __float2bfloat16(x0), h1 = __float2bfloat16(x1);
    float l0 = x0 - __bfloat162float(h0);
    float l1 = x1 - __bfloat162float(h1);
    ((uint32_t*)hi)[i] = pack_bf16(x0, x1);
    ((uint32_t*)lo)[i] = pack_bf16(l0, l1);
}

// ===================== bf16x3 mma.sync GEMM core =====================
// 512 threads, 16 warps (4 n x 4 o), CTA tile 128n x 128o, K chunk 64.
// A: fp32 LDG + in-loop convert, smem double-buffered (overlaps MMA drain).
// B: pre-converted bf16, 2-stage cp.async. One __syncthreads per chunk.

__device__ __forceinline__ void issue_B(uint32_t dstbase,
    const __nv_bfloat16* __restrict__ Whi, const __nv_bfloat16* __restrict__ Wlo,
    int ldw, int ob, int k0, int rs, int q)
{
#pragma unroll
    for (int j = 0; j < 4; j++) {
        int seg = q*4 + j;                         // 0..15: 0-7 hi, 8-15 lo
        uint32_t doff = (seg < 8) ? (uint32_t)(seg*16) : (uint32_t)(128 + (seg - 8)*16);
        const __nv_bfloat16* src = ((seg < 8) ? Whi : Wlo)
                                   + (size_t)(ob + rs)*ldw + k0 + (seg & 7)*8;
        cpa16(dstbase + rs*PITCH + doff, src);
    }
}

template<bool BN>
__device__ __forceinline__ void conv_storeA(char* dststage, const float* ax,
                                            int kA, int rs, int q) {
    float x[16];
#pragma unroll
    for (int j = 0; j < 16; j++) x[j] = ax[j];
    if (BN) {
#pragma unroll
        for (int j = 0; j < 16; j++) {
            float v = fmaf(x[j], g_sc1[kA + j], g_bi1[kA + j]);
            x[j] = (v >= 0.f) ? v : 0.01f*v;
        }
    }
    float lo[16];
#pragma unroll
    for (int j = 0; j < 16; j++) {
        __nv_bfloat16 h = __float2bfloat16(x[j]);
        lo[j] = x[j] - __bfloat162float(h);
    }
    char* arow = dststage + rs*PITCH + q*32;
    *(uint4*)arow = make_uint4(pack_bf16(x[0], x[1]),  pack_bf16(x[2], x[3]),
                               pack_bf16(x[4], x[5]),  pack_bf16(x[6], x[7]));
    *(uint4*)(arow + 16) = make_uint4(pack_bf16(x[8], x[9]),   pack_bf16(x[10], x[11]),
                                      pack_bf16(x[12], x[13]), pack_bf16(x[14], x[15]));
    *(uint4*)(arow + 128) = make_uint4(pack_bf16(lo[0], lo[1]), pack_bf16(lo[2], lo[3]),
                                       pack_bf16(lo[4], lo[5]), pack_bf16(lo[6], lo[7]));
    *(uint4*)(arow + 144) = make_uint4(pack_bf16(lo[8], lo[9]),   pack_bf16(lo[10], lo[11]),
                                       pack_bf16(lo[12], lo[13]), pack_bf16(lo[14], lo[15]));
}

template<bool BN>
__device__ __forceinline__ void gemm_core(char* sm, uint32_t sb,
    const float* __restrict__ A, int ldn, int nb, int kA0,
    const __nv_bfloat16* __restrict__ Whi, const __nv_bfloat16* __restrict__ Wlo,
    int ldw, int ob, int kW0, int nk64, float acc[2][4][4])
{
    int t = threadIdx.x, lane = t & 31, wid = t >> 5;
    int wn = wid & 3, wo = wid >> 2;
    int rs = t & 127, q = t >> 7;
    uint32_t aOff = (uint32_t)((wn*32 + (lane & 15))*PITCH + ((lane >> 4) & 1)*16);
    uint32_t bOff = (uint32_t)((wo*32 + (lane & 7) + ((lane >> 4) & 1)*8)*PITCH
                               + ((lane >> 3) & 1)*16);
    float ax[16];
    // ---- prologue: B(0) cp.async; A(0) LDG+convert into stage0; A(1) LDG ----
    issue_B(sb + O_B0, Whi, Wlo, ldw, ob, kW0, rs, q);
    CP_COMMIT();
    {
        const float* ap = A + (size_t)(kA0 + q*16)*ldn + nb + rs;
#pragma unroll
        for (int j = 0; j < 16; j++) ax[j] = ap[(size_t)j*ldn];
    }
    conv_storeA<BN>(sm + O_A0, ax, q*16, rs, q);
    if (nk64 > 1) {
        const float* ap = A + (size_t)(kA0 + 64 + q*16)*ldn + nb + rs;
#pragma unroll
        for (int j = 0; j < 16; j++) ax[j] = ap[(size_t)j*ldn];
    }
    for (int it = 0; it < nk64; it++) {
        CP_WAIT(0);              // B(it) landed
        __syncthreads();         // A(it) STS visible; stages (it+1)&1 free
        // issue B(it+1) into the freed stage (copy overlaps compute below)
        if (it + 1 < nk64) {
            issue_B(sb + (((it + 1) & 1) ? O_B1 : O_B0), Whi, Wlo, ldw, ob,
                    kW0 + (it + 1)*64, rs, q);
            CP_COMMIT();
        }
        // ---- compute chunk it: term-outer MMA order (8 indep per term) ----
        uint32_t aAddr = sb + ((it & 1) ? O_A1 : O_A0) + aOff;
        uint32_t bAddr = sb + ((it & 1) ? O_B1 : O_B0) + bOff;
#pragma unroll
        for (int s16 = 0; s16 < 4; s16++) {
            uint32_t Ah[2][4], Al[2][4], Bh[2][4], Bl[2][4];
#pragma unroll
            for (int mt = 0; mt < 2; mt++) {
                uint32_t ad = aAddr + mt*16*PITCH + s16*32;
                ldm4(Ah[mt], ad); ldm4(Al[mt], ad + 128);
            }
#pragma unroll
            for (int np = 0; np < 2; np++) {
                uint32_t bd = bAddr + np*16*PITCH + s16*32;
                ldm4(Bh[np], bd); ldm4(Bl[np], bd + 128);
            }
#pragma unroll
            for (int mt = 0; mt < 2; mt++)
#pragma unroll
            for (int nt = 0; nt < 4; nt++)
                mma_bf16(acc[mt][nt], Ah[mt], &Bh[nt >> 1][(nt & 1)*2]);
#pragma unroll
            for (int mt = 0; mt < 2; mt++)
#pragma unroll
            for (int nt = 0; nt < 4; nt++)
                mma_bf16(acc[mt][nt], Ah[mt], &Bl[nt >> 1][(nt & 1)*2]);
#pragma unroll
            for (int mt = 0; mt < 2; mt++)
#pragma unroll
            for (int nt = 0; nt < 4; nt++)
                mma_bf16(acc[mt][nt], Al[mt], &Bh[nt >> 1][(nt & 1)*2]);
        }
        // ---- convert A(it+1) into other stage; LDG A(it+2) (overlap MMA drain) ----
        if (it + 1 < nk64) {
            conv_storeA<BN>(sm + (((it + 1) & 1) ? O_A1 : O_A0), ax,
                            (it + 1)*64 + q*16, rs, q);
            if (it + 2 < nk64) {
                const float* ap = A + (size_t)(kA0 + (it + 2)*64 + q*16)*ldn + nb + rs;
#pragma unroll
                for (int j = 0; j < 16; j++) ax[j] = ap[(size_t)j*ldn];
            }
        }
    }
    __syncthreads();
}

// dump one 32-o strip of accumulators into sbuf[o_local][n]
__device__ __forceinline__ void dump_strip(float* sbuf, int s, float acc[2][4][4]) {
    int t = threadIdx.x, lane = t & 31, wid = t >> 5;
    int wn = wid & 3, wo = wid >> 2;
    if (wo != s) return;
    int g = lane >> 2, c2 = (lane & 3)*2;
#pragma unroll
    for (int mt = 0; mt < 2; mt++)
#pragma unroll
    for (int nt = 0; nt < 4; nt++) {
        int nl = wn*32 + mt*16 + g;
        int ol = nt*8 + c2;
        sbuf[ol*132 + nl]         = acc[mt][nt][0];
        sbuf[(ol+1)*132 + nl]     = acc[mt][nt][1];
        sbuf[ol*132 + nl + 8]     = acc[mt][nt][2];
        sbuf[(ol+1)*132 + nl + 8] = acc[mt][nt][3];
    }
}

// ---------- GEMM 1a: Gt[b][n][o] = W1[:, :512] @ feat ----------
__global__ __launch_bounds__(512, 1)
void gemm1a_kernel(const float* __restrict__ feat) {
    extern __shared__ __align__(16) char sm[];
    uint32_t sb = smem_u32(sm);
    int b = blockIdx.z, nb = blockIdx.x*128, ob = blockIdx.y*128;
    int t = threadIdx.x;
    float acc[2][4][4] = {};
    gemm_core<false>(sm, sb, feat + (size_t)b*CPf*NP, NP, nb, 0,
                     g_W1_hi, g_W1_lo, KW, ob, 0, CPf/64, acc);
    float* sbuf = (float*)(sm + O_SBUF);
    int n = t & 127, oq = t >> 7;
    for (int s = 0; s < 4; s++) {
        __syncthreads();
        dump_strip(sbuf, s, acc);
        __syncthreads();
        float f[8];
#pragma unroll
        for (int j = 0; j < 8; j++) f[j] = sbuf[(oq*8 + j)*132 + n];
        float* dst = &g_Gt[((size_t)b*NP + nb + n)*C1f + ob + s*32 + oq*8];
        *(float4*)dst       = make_float4(f[0], f[1], f[2], f[3]);
        *(float4*)(dst + 4) = make_float4(f[4], f[5], f[6], f[7]);
    }
}

// shared epilogue: optional gather, transpose writeout [o][n], BN-stat partials
__device__ __forceinline__ void epi_write(char* sm, float acc[2][4][4],
                                          float* __restrict__ Y, int nb, int ob,
                                          int b, bool gather) {
    int t = threadIdx.x;
    float* sbuf = (float*)(sm + O_SBUF);
    int*   sid  = (int*)(sm + O_SID);
    float* swt  = (float*)(sm + O_SWT);
    float* chs  = (float*)(sm + O_CHS);
    float* chq  = (float*)(sm + O_CHQ);
    if (gather) {
        for (int i = t; i < 384; i += 512) {
            size_t base = ((size_t)b*N0 + nb)*3 + i;
            sid[i] = g_idx[base]; swt[i] = g_wt[base];
        }
    }
    const float* Gt = g_Gt + (size_t)b*NP*C1f;
    for (int s = 0; s < 4; s++) {
        __syncthreads();
        dump_strip(sbuf, s, acc);
        __syncthreads();
        if (gather) {
            int n = t & 127, oq = t >> 7;
            float v[8];
#pragma unroll
            for (int j = 0; j < 8; j++) v[j] = sbuf[(oq*8 + j)*132 + n];
#pragma unroll
            for (int k = 0; k < 3; k++) {
                int   id = sid[n*3 + k];
                float wk = swt[n*3 + k];
                const float* gp = &Gt[(size_t)id*C1f + ob + s*32 + oq*8];
                float4 g0 = *(const float4*)gp;
                float4 g1 = *(const float4*)(gp + 4);
                v[0] = fmaf(wk, g0.x, v[0]); v[1] = fmaf(wk, g0.y, v[1]);
                v[2] = fmaf(wk, g0.z, v[2]); v[3] = fmaf(wk, g0.w, v[3]);
                v[4] = fmaf(wk, g1.x, v[4]); v[5] = fmaf(wk, g1.y, v[5]);
                v[6] = fmaf(wk, g1.z, v[6]); v[7] = fmaf(wk, g1.w, v[7]);
            }
#pragma unroll
            for (int j = 0; j < 8; j++) sbuf[(oq*8 + j)*132 + n] = v[j];
            __syncthreads();
        }
        {
            int ol = t >> 4, seg = t & 15, n = seg*8;
            const float* srow = &sbuf[ol*132 + n];
            float4 x0 = *(const float4*)srow;
            float4 x1 = *(const float4*)(srow + 4);
            float s1 = x0.x + x0.y + x0.z + x0.w + x1.x + x1.y + x1.z + x1.w;
            float s2 = 0.f;
            s2 = fmaf(x0.x, x0.x, s2); s2 = fmaf(x0.y, x0.y, s2);
            s2 = fmaf(x0.z, x0.z, s2); s2 = fmaf(x0.w, x0.w, s2);
            s2 = fmaf(x1.x, x1.x, s2); s2 = fmaf(x1.y, x1.y, s2);
            s2 = fmaf(x1.z, x1.z, s2); s2 = fmaf(x1.w, x1.w, s2);
            float* dst = &Y[(size_t)(ob + s*32 + ol)*N0 + nb + n];
            *(float4*)dst       = x0;
            *(float4*)(dst + 4) = x1;
#pragma unroll
            for (int off = 8; off; off >>= 1) {
                s1 += __shfl_down_sync(0xffffffffu, s1, off, 16);
                s2 += __shfl_down_sync(0xffffffffu, s2, off, 16);
            }
            if (seg == 0) { chs[s*32 + ol] = s1; chq[s*32 + ol] = s2; }
        }
    }
    __syncthreads();
    if (t < 128) {
        int pidx = blockIdx.x + 64*blockIdx.z;
        g_p1[(size_t)(ob + t)*512 + pidx] = chs[t];
        g_p2[(size_t)(ob + t)*512 + pidx] = chq[t];
    }
}

// ---- GEMM 1b: y1 = W1[:, 512:] @ skip + interp(Gt); fused stats ----
__global__ __launch_bounds__(512, 1)
void gemm1b_kernel(const float* __restrict__ skip) {
    extern __shared__ __align__(16) char sm[];
    uint32_t sb = smem_u32(sm);
    int b = blockIdx.z, nb = blockIdx.x*128, ob = blockIdx.y*128;
    float acc[2][4][4] = {};
    gemm_core<false>(sm, sb, skip + (size_t)b*CSf*N0, N0, nb, 0,
                     g_W1_hi, g_W1_lo, KW, ob, CPf, CSf/64, acc);
    epi_write(sm, acc, g_y1 + (size_t)b*C1f*N0, nb, ob, b, true);
}

// ---- GEMM 2: z = W2 @ lrelu(BN1(y1)); BN on A-stage; fused stats ----
__global__ __launch_bounds__(512, 1)
void gemm2_kernel() {
    extern __shared__ __align__(16) char sm[];
    uint32_t sb = smem_u32(sm);
    int b = blockIdx.z, nb = blockIdx.x*128, ob = blockIdx.y*128;
    float acc[2][4][4] = {};
    gemm_core<true>(sm, sb, g_y1 + (size_t)b*C1f*N0, N0, nb, 0,
                    g_W2_hi, g_W2_lo, C1f, ob, 0, C1f/64, acc);
    epi_write(sm, acc, g_z + (size_t)b*C2f*N0, nb, ob, b, false);
}

// ---------------- stats reduce ----------------
__global__ void stats_reduce(const float* __restrict__ gain,
                             const float* __restrict__ beta, int layer) {
    int o = blockIdx.x, t = threadIdx.x;
    const float* p1 = &g_p1[(size_t)o*512];
    const float* p2 = &g_p2[(size_t)o*512];
    float a = p1[t] + p1[t+128] + p1[t+256] + p1[t+384];
    float c = p2[t] + p2[t+128] + p2[t+256] + p2[t+384];
    __shared__ float r1[128], r2[128];
    r1[t] = a; r2[t] = c; __syncthreads();
    for (int h = 64; h > 0; h >>= 1) {
        if (t < h) { r1[t] += r1[t+h]; r2[t] += r2[t+h]; }
        __syncthreads();
    }
    if (t == 0) {
        const float invN = 1.0f/((float)BB*N0);
        float m   = r1[0]*invN;
        float var = r2[0]*invN - m*m;
        float sc  = gain[o] * (1.0f/sqrtf(var + 1e-3f));
        if (layer) { g_sc2[o] = sc; g_bi2[o] = beta[o] - m*sc; }
        else       { g_sc1[o] = sc; g_bi1[o] = beta[o] - m*sc; }
    }
}

// ---------------- output: lrelu(BN2(z)) ----------------
__global__ void out_kernel(float* __restrict__ out) {
    size_t i = (size_t)blockIdx.x*blockDim.x + threadIdx.x;
    const size_t total4 = (size_t)BB*C2f*N0/4;
    if (i >= total4) return;
    int ch = (int)((i/(N0/4)) % C2f);
    float sc = g_sc2[ch], bi = g_bi2[ch];
    float4 v = *((const float4*)g_z + i);
    v.x = fmaf(v.x, sc, bi); v.x = (v.x >= 0.f) ? v.x : 0.01f*v.x;
    v.y = fmaf(v.y, sc, bi); v.y = (v.y >= 0.f) ? v.y : 0.01f*v.y;
    v.z = fmaf(v.z, sc, bi); v.z = (v.z >= 0.f) ? v.z : 0.01f*v.z;
    v.w = fmaf(v.w, sc, bi); v.w = (v.w >= 0.f) ? v.w : 0.01f*v.w;
    *((float4*)out + i) = v;
}

// ---------------- launch ----------------
extern "C" void kernel_launch(void* const* d_in, const int* in_sizes, int n_in,
                              void* d_out, int out_size) {
    const float* xyz   = (const float*)d_in[0];
    const float* skip  = (const float*)d_in[1];
    const float* xyzp  = (const float*)d_in[2];
    const float* featp = (const float*)d_in[3];
    const float* W1    = (const float*)d_in[4];
    const float* g1    = (const float*)d_in[5];
    const float* b1    = (const float*)d_in[6];
    const float* W2    = (const float*)d_in[7];
    const float* g2    = (const float*)d_in[8];
    const float* b2    = (const float*)d_in[9];
    float* out = (float*)d_out;

    static int s_attr = 0;
    if (!s_attr) {
        cudaFuncSetAttribute(gemm1a_kernel, cudaFuncAttributeMaxDynamicSharedMemorySize, SM_BYTES);
        cudaFuncSetAttribute(gemm1b_kernel, cudaFuncAttributeMaxDynamicSharedMemorySize, SM_BYTES);
        cudaFuncSetAttribute(gemm2_kernel,  cudaFuncAttributeMaxDynamicSharedMemorySize, SM_BYTES);
        s_attr = 1;
    }

    __nv_bfloat16 *w1_hi, *w1_lo, *w2_hi, *w2_lo;
    cudaGetSymbolAddress((void**)&w1_hi, g_W1_hi); cudaGetSymbolAddress((void**)&w1_lo, g_W1_lo);
    cudaGetSymbolAddress((void**)&w2_hi, g_W2_hi); cudaGetSymbolAddress((void**)&w2_lo, g_W2_lo);

    const size_t xyz_elems = (size_t)BB*3*N0;
    const size_t nf_elems  = (size_t)BB*C2f*N0;
    size_t off = 0;
    if ((size_t)out_size >= xyz_elems + nf_elems) {
        cudaMemcpyAsync(out, xyz, xyz_elems*sizeof(float), cudaMemcpyDeviceToDevice);
        off = xyz_elems;
    }

    knn_kernel   <<<dim3(N0/256, BB), 256>>>(xyz, xyzp);
    wconv_kernel <<<(C1f*KW/2 + 255)/256,  256>>>(W1, w1_hi, w1_lo, C1f*KW/2);
    wconv_kernel <<<(C2f*C1f/2 + 255)/256, 256>>>(W2, w2_hi, w2_lo, C2f*C1f/2);
    gemm1a_kernel<<<dim3(NP/128, C1f/128, BB), 512, SM_BYTES>>>(featp);
    gemm1b_kernel<<<dim3(N0/128, C1f/128, BB), 512, SM_BYTES>>>(skip);
    stats_reduce <<<C1f, 128>>>(g1, b1, 0);
    gemm2_kernel <<<dim3(N0/128, C2f/128, BB), 512, SM_BYTES>>>();
    stats_reduce <<<C2f, 128>>>(g2, b2, 1);
    out_kernel   <<<(unsigned)((nf_elems/4 + 255)/256), 256>>>(out + off);
}

// round 9
// speedup vs baseline: 1.6010x; 1.2033x over previous
#include <cuda_runtime.h>
#include <cuda_fp16.h>
#include <cstdint>

#define BB  8
#define N0  8192
#define NP  2048
#define CPf 512
#define CSf 256
#define C1f 256
#define C2f 256
#define KW  768   // CP+CS

// A smem row: 64 fp16 hi (128B) | 64 fp16 lo (128B) | pad 16B
#define PITCH_A 272
// B smem row: 64 fp16 (128B) | pad 16B
#define PITCH_B 144
#define O_A0  0
#define O_A1  34816
#define O_B0  69632
#define O_B1  88064
#define SM_BYTES 106496
// epilogue overlays (inside A0 region, used after mainloop)
#define O_SBUF 0                 // 32 x 132 floats
#define O_SID  16896
#define O_SWT  18432
#define O_CHS  19968
#define O_CHQ  20480

// ---------------- scratch (device globals) ----------------
__device__ int   g_idx[BB*N0*3];
__device__ float g_wt [BB*N0*3];
__device__ float g_Gt [BB*NP*C1f];
__device__ float g_y1 [BB*C1f*N0];
__device__ float g_z  [BB*C2f*N0];
__device__ float g_p1 [C1f*512], g_p2[C1f*512];
__device__ float g_sc1[C1f], g_bi1[C1f], g_sc2[C2f], g_bi2[C2f];
// pre-converted weights (fp16, row-major [o][k])
__device__ __align__(16) __half g_W1_h[C1f*KW];
__device__ __align__(16) __half g_W2_h[C2f*C1f];

// ---------------- PTX wrappers (baseline ISA, compute_103-safe) ----------------
__device__ __forceinline__ uint32_t smem_u32(const void* p) {
    uint32_t a;
    asm("{ .reg .u64 t; cvta.to.shared.u64 t, %1; cvt.u32.u64 %0, t; }" : "=r"(a) : "l"(p));
    return a;
}
__device__ __forceinline__ void ldm4(uint32_t* r, uint32_t addr) {
    asm volatile("ldmatrix.sync.aligned.m8n8.x4.shared.b16 {%0,%1,%2,%3}, [%4];"
        : "=r"(r[0]), "=r"(r[1]), "=r"(r[2]), "=r"(r[3]) : "r"(addr));
}
__device__ __forceinline__ void mma_f16(float* d, const uint32_t* a, const uint32_t* b) {
    asm volatile("mma.sync.aligned.m16n8k16.row.col.f32.f16.f16.f32 "
        "{%0,%1,%2,%3}, {%4,%5,%6,%7}, {%8,%9}, {%0,%1,%2,%3};"
        : "+f"(d[0]), "+f"(d[1]), "+f"(d[2]), "+f"(d[3])
        : "r"(a[0]), "r"(a[1]), "r"(a[2]), "r"(a[3]), "r"(b[0]), "r"(b[1]));
}
__device__ __forceinline__ uint32_t pack_h2(float a, float b) {
    __half2 p = __floats2half2_rn(a, b);
    return *(uint32_t*)&p;
}
__device__ __forceinline__ void cpa16(uint32_t dst, const void* src) {
    asm volatile("cp.async.cg.shared.global [%0], [%1], 16;" :: "r"(dst), "l"(src) : "memory");
}
#define CP_COMMIT() asm volatile("cp.async.commit_group;" ::: "memory")
#define CP_WAIT(n)  asm volatile("cp.async.wait_group %0;" :: "n"(n) : "memory")

// ---------------- kNN ----------------
__global__ void knn_kernel(const float* __restrict__ xyz,
                           const float* __restrict__ xyzp) {
    __shared__ float4 sp[NP];
    int b = blockIdx.y;
    const float* p = xyzp + (size_t)b*3*NP;
    for (int j = threadIdx.x; j < NP; j += blockDim.x) {
        float X = p[j], Y = p[NP + j], Z = p[2*NP + j];
        sp[j] = make_float4(X, Y, Z, X*X + Y*Y + Z*Z);
    }
    __syncthreads();
    int n = blockIdx.x*blockDim.x + threadIdx.x;
    const float* q = xyz + (size_t)b*3*N0;
    float qx = q[n], qy = q[N0 + n], qz = q[2*N0 + n];
    float q2 = qx*qx + qy*qy + qz*qz;
    float d0 = 1e30f, d1 = 1e30f, d2 = 1e30f;
    int   i0 = 0, i1 = 0, i2 = 0;
#pragma unroll 4
    for (int j = 0; j < NP; ++j) {
        float4 v = sp[j];
        float dot = qx*v.x + qy*v.y + qz*v.z;
        float d = (q2 + v.w) - 2.0f*dot;
        if (d < d2) {
            if (d < d1) {
                d2 = d1; i2 = i1;
                if (d < d0) { d1 = d0; i1 = i0; d0 = d; i0 = j; }
                else        { d1 = d;  i1 = j; }
            } else { d2 = d; i2 = j; }
        }
    }
    float e0 = 1.0f/(fmaxf(d0, 1e-10f) + 1e-8f);
    float e1 = 1.0f/(fmaxf(d1, 1e-10f) + 1e-8f);
    float e2 = 1.0f/(fmaxf(d2, 1e-10f) + 1e-8f);
    float inv = 1.0f/(e0 + e1 + e2);
    size_t base = ((size_t)b*N0 + n)*3;
    g_idx[base]   = i0; g_idx[base+1] = i1; g_idx[base+2] = i2;
    g_wt [base]   = e0*inv; g_wt[base+1] = e1*inv; g_wt[base+2] = e2*inv;
}

// ---------------- weight convert (elementwise, fp16 single) ----------------
__global__ void wconv_kernel(const float* __restrict__ w,
                             __half* __restrict__ hi, int npairs) {
    int i = blockIdx.x*blockDim.x + threadIdx.x;
    if (i >= npairs) return;
    ((uint32_t*)hi)[i] = pack_h2(w[2*i], w[2*i + 1]);
}

// ===================== fp16x2 mma.sync GEMM core =====================
// 512 threads, 16 warps (4 n x 4 o), CTA tile 128n x 128o, K chunk 64.
// A = Ah + Al (exact fp16 split, in-loop convert, double-buffered smem).
// B = fp16-rounded (pre-converted), 2-stage cp.async. One __syncthreads per chunk.

__device__ __forceinline__ void issue_B(uint32_t dstbase,
    const __half* __restrict__ Wh, int ldw, int ob, int k0, int rs, int q)
{
    const __half* src = Wh + (size_t)(ob + rs)*ldw + k0 + q*16;
    uint32_t dst = dstbase + rs*PITCH_B + q*32;
    cpa16(dst, src);
    cpa16(dst + 16, src + 8);
}

template<bool BN>
__device__ __forceinline__ void conv_storeA(char* dststage, const float* ax,
                                            int kA, int rs, int q) {
    float x[16];
#pragma unroll
    for (int j = 0; j < 16; j++) x[j] = ax[j];
    if (BN) {
#pragma unroll
        for (int j = 0; j < 16; j++) {
            float v = fmaf(x[j], g_sc1[kA + j], g_bi1[kA + j]);
            x[j] = (v >= 0.f) ? v : 0.01f*v;
        }
    }
    float lo[16];
#pragma unroll
    for (int j = 0; j < 16; j++) {
        __half h = __float2half(x[j]);
        lo[j] = x[j] - __half2float(h);
    }
    char* arow = dststage + rs*PITCH_A + q*32;
    *(uint4*)arow = make_uint4(pack_h2(x[0], x[1]),  pack_h2(x[2], x[3]),
                               pack_h2(x[4], x[5]),  pack_h2(x[6], x[7]));
    *(uint4*)(arow + 16) = make_uint4(pack_h2(x[8], x[9]),   pack_h2(x[10], x[11]),
                                      pack_h2(x[12], x[13]), pack_h2(x[14], x[15]));
    *(uint4*)(arow + 128) = make_uint4(pack_h2(lo[0], lo[1]), pack_h2(lo[2], lo[3]),
                                       pack_h2(lo[4], lo[5]), pack_h2(lo[6], lo[7]));
    *(uint4*)(arow + 144) = make_uint4(pack_h2(lo[8], lo[9]),   pack_h2(lo[10], lo[11]),
                                       pack_h2(lo[12], lo[13]), pack_h2(lo[14], lo[15]));
}

template<bool BN>
__device__ __forceinline__ void gemm_core(char* sm, uint32_t sb,
    const float* __restrict__ A, int ldn, int nb, int kA0,
    const __half* __restrict__ Wh, int ldw, int ob, int kW0,
    int nk64, float acc[2][4][4])
{
    int t = threadIdx.x, lane = t & 31, wid = t >> 5;
    int wn = wid & 3, wo = wid >> 2;
    int rs = t & 127, q = t >> 7;
    uint32_t aOff = (uint32_t)((wn*32 + (lane & 15))*PITCH_A + ((lane >> 4) & 1)*16);
    uint32_t bOff = (uint32_t)((wo*32 + (lane & 7) + ((lane >> 4) & 1)*8)*PITCH_B
                               + ((lane >> 3) & 1)*16);
    float ax[16];
    // ---- prologue: B(0) cp.async; A(0) LDG+convert into stage0; A(1) LDG ----
    issue_B(sb + O_B0, Wh, ldw, ob, kW0, rs, q);
    CP_COMMIT();
    {
        const float* ap = A + (size_t)(kA0 + q*16)*ldn + nb + rs;
#pragma unroll
        for (int j = 0; j < 16; j++) ax[j] = ap[(size_t)j*ldn];
    }
    conv_storeA<BN>(sm + O_A0, ax, q*16, rs, q);
    if (nk64 > 1) {
        const float* ap = A + (size_t)(kA0 + 64 + q*16)*ldn + nb + rs;
#pragma unroll
        for (int j = 0; j < 16; j++) ax[j] = ap[(size_t)j*ldn];
    }
    for (int it = 0; it < nk64; it++) {
        CP_WAIT(0);              // B(it) landed
        __syncthreads();         // A(it) STS visible; stages (it+1)&1 free
        if (it + 1 < nk64) {
            issue_B(sb + (((it + 1) & 1) ? O_B1 : O_B0), Wh, ldw, ob,
                    kW0 + (it + 1)*64, rs, q);
            CP_COMMIT();
        }
        // ---- compute chunk it: 2 terms (AhBh, AlBh), 8 independent per term ----
        uint32_t aAddr = sb + ((it & 1) ? O_A1 : O_A0) + aOff;
        uint32_t bAddr = sb + ((it & 1) ? O_B1 : O_B0) + bOff;
#pragma unroll
        for (int s16 = 0; s16 < 4; s16++) {
            uint32_t Ah[2][4], Al[2][4], Bh[2][4];
#pragma unroll
            for (int mt = 0; mt < 2; mt++) {
                uint32_t ad = aAddr + mt*16*PITCH_A + s16*32;
                ldm4(Ah[mt], ad); ldm4(Al[mt], ad + 128);
            }
#pragma unroll
            for (int np = 0; np < 2; np++)
                ldm4(Bh[np], bAddr + np*16*PITCH_B + s16*32);
#pragma unroll
            for (int mt = 0; mt < 2; mt++)
#pragma unroll
            for (int nt = 0; nt < 4; nt++)
                mma_f16(acc[mt][nt], Ah[mt], &Bh[nt >> 1][(nt & 1)*2]);
#pragma unroll
            for (int mt = 0; mt < 2; mt++)
#pragma unroll
            for (int nt = 0; nt < 4; nt++)
                mma_f16(acc[mt][nt], Al[mt], &Bh[nt >> 1][(nt & 1)*2]);
        }
        // ---- convert A(it+1) into other stage; LDG A(it+2) (overlap MMA drain) ----
        if (it + 1 < nk64) {
            conv_storeA<BN>(sm + (((it + 1) & 1) ? O_A1 : O_A0), ax,
                            (it + 1)*64 + q*16, rs, q);
            if (it + 2 < nk64) {
                const float* ap = A + (size_t)(kA0 + (it + 2)*64 + q*16)*ldn + nb + rs;
#pragma unroll
                for (int j = 0; j < 16; j++) ax[j] = ap[(size_t)j*ldn];
            }
        }
    }
    __syncthreads();
}

// dump one 32-o strip of accumulators into sbuf[o_local][n]
__device__ __forceinline__ void dump_strip(float* sbuf, int s, float acc[2][4][4]) {
    int t = threadIdx.x, lane = t & 31, wid = t >> 5;
    int wn = wid & 3, wo = wid >> 2;
    if (wo != s) return;
    int g = lane >> 2, c2 = (lane & 3)*2;
#pragma unroll
    for (int mt = 0; mt < 2; mt++)
#pragma unroll
    for (int nt = 0; nt < 4; nt++) {
        int nl = wn*32 + mt*16 + g;
        int ol = nt*8 + c2;
        sbuf[ol*132 + nl]         = acc[mt][nt][0];
        sbuf[(ol+1)*132 + nl]     = acc[mt][nt][1];
        sbuf[ol*132 + nl + 8]     = acc[mt][nt][2];
        sbuf[(ol+1)*132 + nl + 8] = acc[mt][nt][3];
    }
}

// ---------- GEMM 1a: Gt[b][n][o] = W1[:, :512] @ feat ----------
__global__ __launch_bounds__(512, 1)
void gemm1a_kernel(const float* __restrict__ feat) {
    extern __shared__ __align__(16) char sm[];
    uint32_t sb = smem_u32(sm);
    int b = blockIdx.z, nb = blockIdx.x*128, ob = blockIdx.y*128;
    int t = threadIdx.x;
    float acc[2][4][4] = {};
    gemm_core<false>(sm, sb, feat + (size_t)b*CPf*NP, NP, nb, 0,
                     g_W1_h, KW, ob, 0, CPf/64, acc);
    float* sbuf = (float*)(sm + O_SBUF);
    int n = t & 127, oq = t >> 7;
    for (int s = 0; s < 4; s++) {
        __syncthreads();
        dump_strip(sbuf, s, acc);
        __syncthreads();
        float f[8];
#pragma unroll
        for (int j = 0; j < 8; j++) f[j] = sbuf[(oq*8 + j)*132 + n];
        float* dst = &g_Gt[((size_t)b*NP + nb + n)*C1f + ob + s*32 + oq*8];
        *(float4*)dst       = make_float4(f[0], f[1], f[2], f[3]);
        *(float4*)(dst + 4) = make_float4(f[4], f[5], f[6], f[7]);
    }
}

// shared epilogue: optional gather, transpose writeout [o][n], BN-stat partials
__device__ __forceinline__ void epi_write(char* sm, float acc[2][4][4],
                                          float* __restrict__ Y, int nb, int ob,
                                          int b, bool gather) {
    int t = threadIdx.x;
    float* sbuf = (float*)(sm + O_SBUF);
    int*   sid  = (int*)(sm + O_SID);
    float* swt  = (float*)(sm + O_SWT);
    float* chs  = (float*)(sm + O_CHS);
    float* chq  = (float*)(sm + O_CHQ);
    if (gather) {
        for (int i = t; i < 384; i += 512) {
            size_t base = ((size_t)b*N0 + nb)*3 + i;
            sid[i] = g_idx[base]; swt[i] = g_wt[base];
        }
    }
    const float* Gt = g_Gt + (size_t)b*NP*C1f;
    for (int s = 0; s < 4; s++) {
        __syncthreads();
        dump_strip(sbuf, s, acc);
        __syncthreads();
        if (gather) {
            int n = t & 127, oq = t >> 7;
            float v[8];
#pragma unroll
            for (int j = 0; j < 8; j++) v[j] = sbuf[(oq*8 + j)*132 + n];
#pragma unroll
            for (int k = 0; k < 3; k++) {
                int   id = sid[n*3 + k];
                float wk = swt[n*3 + k];
                const float* gp = &Gt[(size_t)id*C1f + ob + s*32 + oq*8];
                float4 g0 = *(const float4*)gp;
                float4 g1 = *(const float4*)(gp + 4);
                v[0] = fmaf(wk, g0.x, v[0]); v[1] = fmaf(wk, g0.y, v[1]);
                v[2] = fmaf(wk, g0.z, v[2]); v[3] = fmaf(wk, g0.w, v[3]);
                v[4] = fmaf(wk, g1.x, v[4]); v[5] = fmaf(wk, g1.y, v[5]);
                v[6] = fmaf(wk, g1.z, v[6]); v[7] = fmaf(wk, g1.w, v[7]);
            }
#pragma unroll
            for (int j = 0; j < 8; j++) sbuf[(oq*8 + j)*132 + n] = v[j];
            __syncthreads();
        }
        {
            int ol = t >> 4, seg = t & 15, n = seg*8;
            const float* srow = &sbuf[ol*132 + n];
            float4 x0 = *(const float4*)srow;
            float4 x1 = *(const float4*)(srow + 4);
            float s1 = x0.x + x0.y + x0.z + x0.w + x1.x + x1.y + x1.z + x1.w;
            float s2 = 0.f;
            s2 = fmaf(x0.x, x0.x, s2); s2 = fmaf(x0.y, x0.y, s2);
            s2 = fmaf(x0.z, x0.z, s2); s2 = fmaf(x0.w, x0.w, s2);
            s2 = fmaf(x1.x, x1.x, s2); s2 = fmaf(x1.y, x1.y, s2);
            s2 = fmaf(x1.z, x1.z, s2); s2 = fmaf(x1.w, x1.w, s2);
            float* dst = &Y[(size_t)(ob + s*32 + ol)*N0 + nb + n];
            *(float4*)dst       = x0;
            *(float4*)(dst + 4) = x1;
#pragma unroll
            for (int off = 8; off; off >>= 1) {
                s1 += __shfl_down_sync(0xffffffffu, s1, off, 16);
                s2 += __shfl_down_sync(0xffffffffu, s2, off, 16);
            }
            if (seg == 0) { chs[s*32 + ol] = s1; chq[s*32 + ol] = s2; }
        }
    }
    __syncthreads();
    if (t < 128) {
        int pidx = blockIdx.x + 64*blockIdx.z;
        g_p1[(size_t)(ob + t)*512 + pidx] = chs[t];
        g_p2[(size_t)(ob + t)*512 + pidx] = chq[t];
    }
}

// ---- GEMM 1b: y1 = W1[:, 512:] @ skip + interp(Gt); fused stats ----
__global__ __launch_bounds__(512, 1)
void gemm1b_kernel(const float* __restrict__ skip) {
    extern __shared__ __align__(16) char sm[];
    uint32_t sb = smem_u32(sm);
    int b = blockIdx.z, nb = blockIdx.x*128, ob = blockIdx.y*128;
    float acc[2][4][4] = {};
    gemm_core<false>(sm, sb, skip + (size_t)b*CSf*N0, N0, nb, 0,
                     g_W1_h, KW, ob, CPf, CSf/64, acc);
    epi_write(sm, acc, g_y1 + (size_t)b*C1f*N0, nb, ob, b, true);
}

// ---- GEMM 2: z = W2 @ lrelu(BN1(y1)); BN on A-stage; fused stats ----
__global__ __launch_bounds__(512, 1)
void gemm2_kernel() {
    extern __shared__ __align__(16) char sm[];
    uint32_t sb = smem_u32(sm);
    int b = blockIdx.z, nb = blockIdx.x*128, ob = blockIdx.y*128;
    float acc[2][4][4] = {};
    gemm_core<true>(sm, sb, g_y1 + (size_t)b*C1f*N0, N0, nb, 0,
                    g_W2_h, C1f, ob, 0, C1f/64, acc);
    epi_write(sm, acc, g_z + (size_t)b*C2f*N0, nb, ob, b, false);
}

// ---------------- stats reduce ----------------
__global__ void stats_reduce(const float* __restrict__ gain,
                             const float* __restrict__ beta, int layer) {
    int o = blockIdx.x, t = threadIdx.x;
    const float* p1 = &g_p1[(size_t)o*512];
    const float* p2 = &g_p2[(size_t)o*512];
    float a = p1[t] + p1[t+128] + p1[t+256] + p1[t+384];
    float c = p2[t] + p2[t+128] + p2[t+256] + p2[t+384];
    __shared__ float r1[128], r2[128];
    r1[t] = a; r2[t] = c; __syncthreads();
    for (int h = 64; h > 0; h >>= 1) {
        if (t < h) { r1[t] += r1[t+h]; r2[t] += r2[t+h]; }
        __syncthreads();
    }
    if (t == 0) {
        const float invN = 1.0f/((float)BB*N0);
        float m   = r1[0]*invN;
        float var = r2[0]*invN - m*m;
        float sc  = gain[o] * (1.0f/sqrtf(var + 1e-3f));
        if (layer) { g_sc2[o] = sc; g_bi2[o] = beta[o] - m*sc; }
        else       { g_sc1[o] = sc; g_bi1[o] = beta[o] - m*sc; }
    }
}

// ---------------- output: lrelu(BN2(z)) ----------------
__global__ void out_kernel(float* __restrict__ out) {
    size_t i = (size_t)blockIdx.x*blockDim.x + threadIdx.x;
    const size_t total4 = (size_t)BB*C2f*N0/4;
    if (i >= total4) return;
    int ch = (int)((i/(N0/4)) % C2f);
    float sc = g_sc2[ch], bi = g_bi2[ch];
    float4 v = *((const float4*)g_z + i);
    v.x = fmaf(v.x, sc, bi); v.x = (v.x >= 0.f) ? v.x : 0.01f*v.x;
    v.y = fmaf(v.y, sc, bi); v.y = (v.y >= 0.f) ? v.y : 0.01f*v.y;
    v.z = fmaf(v.z, sc, bi); v.z = (v.z >= 0.f) ? v.z : 0.01f*v.z;
    v.w = fmaf(v.w, sc, bi); v.w = (v.w >= 0.f) ? v.w : 0.01f*v.w;
    *((float4*)out + i) = v;
}

// ---------------- launch ----------------
extern "C" void kernel_launch(void* const* d_in, const int* in_sizes, int n_in,
                              void* d_out, int out_size) {
    const float* xyz   = (const float*)d_in[0];
    const float* skip  = (const float*)d_in[1];
    const float* xyzp  = (const float*)d_in[2];
    const float* featp = (const float*)d_in[3];
    const float* W1    = (const float*)d_in[4];
    const float* g1    = (const float*)d_in[5];
    const float* b1    = (const float*)d_in[6];
    const float* W2    = (const float*)d_in[7];
    const float* g2    = (const float*)d_in[8];
    const float* b2    = (const float*)d_in[9];
    float* out = (float*)d_out;

    static int s_attr = 0;
    if (!s_attr) {
        cudaFuncSetAttribute(gemm1a_kernel, cudaFuncAttributeMaxDynamicSharedMemorySize, SM_BYTES);
        cudaFuncSetAttribute(gemm1b_kernel, cudaFuncAttributeMaxDynamicSharedMemorySize, SM_BYTES);
        cudaFuncSetAttribute(gemm2_kernel,  cudaFuncAttributeMaxDynamicSharedMemorySize, SM_BYTES);
        s_attr = 1;
    }

    __half *w1_h, *w2_h;
    cudaGetSymbolAddress((void**)&w1_h, g_W1_h);
    cudaGetSymbolAddress((void**)&w2_h, g_W2_h);

    const size_t xyz_elems = (size_t)BB*3*N0;
    const size_t nf_elems  = (size_t)BB*C2f*N0;
    size_t off = 0;
    if ((size_t)out_size >= xyz_elems + nf_elems) {
        cudaMemcpyAsync(out, xyz, xyz_elems*sizeof(float), cudaMemcpyDeviceToDevice);
        off = xyz_elems;
    }

    knn_kernel   <<<dim3(N0/256, BB), 256>>>(xyz, xyzp);
    wconv_kernel <<<(C1f*KW/2 + 255)/256,  256>>>(W1, w1_h, C1f*KW/2);
    wconv_kernel <<<(C2f*C1f/2 + 255)/256, 256>>>(W2, w2_h, C2f*C1f/2);
    gemm1a_kernel<<<dim3(NP/128, C1f/128, BB), 512, SM_BYTES>>>(featp);
    gemm1b_kernel<<<dim3(N0/128, C1f/128, BB), 512, SM_BYTES>>>(skip);
    stats_reduce <<<C1f, 128>>>(g1, b1, 0);
    gemm2_kernel <<<dim3(N0/128, C2f/128, BB), 512, SM_BYTES>>>();
    stats_reduce <<<C2f, 128>>>(g2, b2, 1);
    out_kernel   <<<(unsigned)((nf_elems/4 + 255)/256), 256>>>(out + off);
}

// round 10
// speedup vs baseline: 1.7565x; 1.0971x over previous
#include <cuda_runtime.h>
#include <cuda_fp16.h>
#include <cstdint>

#define BB  8
#define N0  8192
#define NP  2048
#define CPf 512
#define CSf 256
#define C1f 256
#define C2f 256
#define KW  768   // CP+CS

// smem row (A and B): 64 fp16 (128B) | pad 16B
#define PITCH_A 144
#define PITCH_B 144
#define O_A0  0
#define O_A1  18432
#define O_B0  36864
#define O_B1  55296
#define SM_BYTES 73728
// epilogue overlays (inside A region, used after mainloop)
#define O_SBUF 0                 // 32 x 132 floats
#define O_SID  16896
#define O_SWT  18432
#define O_CHS  19968
#define O_CHQ  20480

// ---------------- scratch (device globals) ----------------
__device__ int   g_idx[BB*N0*3];
__device__ float g_wt [BB*N0*3];
__device__ float g_Gt [BB*NP*C1f];
__device__ float g_y1 [BB*C1f*N0];
__device__ float g_z  [BB*C2f*N0];
__device__ float g_p1 [C1f*512], g_p2[C1f*512];
__device__ float g_sc1[C1f], g_bi1[C1f], g_sc2[C2f], g_bi2[C2f];
// pre-converted weights (fp16, row-major [o][k])
__device__ __align__(16) __half g_W1_h[C1f*KW];
__device__ __align__(16) __half g_W2_h[C2f*C1f];

// ---------------- PTX wrappers (baseline ISA, compute_103-safe) ----------------
__device__ __forceinline__ uint32_t smem_u32(const void* p) {
    uint32_t a;
    asm("{ .reg .u64 t; cvta.to.shared.u64 t, %1; cvt.u32.u64 %0, t; }" : "=r"(a) : "l"(p));
    return a;
}
__device__ __forceinline__ void ldm4(uint32_t* r, uint32_t addr) {
    asm volatile("ldmatrix.sync.aligned.m8n8.x4.shared.b16 {%0,%1,%2,%3}, [%4];"
        : "=r"(r[0]), "=r"(r[1]), "=r"(r[2]), "=r"(r[3]) : "r"(addr));
}
__device__ __forceinline__ void mma_f16(float* d, const uint32_t* a, const uint32_t* b) {
    asm volatile("mma.sync.aligned.m16n8k16.row.col.f32.f16.f16.f32 "
        "{%0,%1,%2,%3}, {%4,%5,%6,%7}, {%8,%9}, {%0,%1,%2,%3};"
        : "+f"(d[0]), "+f"(d[1]), "+f"(d[2]), "+f"(d[3])
        : "r"(a[0]), "r"(a[1]), "r"(a[2]), "r"(a[3]), "r"(b[0]), "r"(b[1]));
}
__device__ __forceinline__ uint32_t pack_h2(float a, float b) {
    __half2 p = __floats2half2_rn(a, b);
    return *(uint32_t*)&p;
}
__device__ __forceinline__ void cpa16(uint32_t dst, const void* src) {
    asm volatile("cp.async.cg.shared.global [%0], [%1], 16;" :: "r"(dst), "l"(src) : "memory");
}
#define CP_COMMIT() asm volatile("cp.async.commit_group;" ::: "memory")
#define CP_WAIT(n)  asm volatile("cp.async.wait_group %0;" :: "n"(n) : "memory")

// ---------------- kNN ----------------
__global__ void knn_kernel(const float* __restrict__ xyz,
                           const float* __restrict__ xyzp) {
    __shared__ float4 sp[NP];
    int b = blockIdx.y;
    const float* p = xyzp + (size_t)b*3*NP;
    for (int j = threadIdx.x; j < NP; j += blockDim.x) {
        float X = p[j], Y = p[NP + j], Z = p[2*NP + j];
        sp[j] = make_float4(X, Y, Z, X*X + Y*Y + Z*Z);
    }
    __syncthreads();
    int n = blockIdx.x*blockDim.x + threadIdx.x;
    const float* q = xyz + (size_t)b*3*N0;
    float qx = q[n], qy = q[N0 + n], qz = q[2*N0 + n];
    float q2 = qx*qx + qy*qy + qz*qz;
    float d0 = 1e30f, d1 = 1e30f, d2 = 1e30f;
    int   i0 = 0, i1 = 0, i2 = 0;
#pragma unroll 4
    for (int j = 0; j < NP; ++j) {
        float4 v = sp[j];
        float dot = qx*v.x + qy*v.y + qz*v.z;
        float d = (q2 + v.w) - 2.0f*dot;
        if (d < d2) {
            if (d < d1) {
                d2 = d1; i2 = i1;
                if (d < d0) { d1 = d0; i1 = i0; d0 = d; i0 = j; }
                else        { d1 = d;  i1 = j; }
            } else { d2 = d; i2 = j; }
        }
    }
    float e0 = 1.0f/(fmaxf(d0, 1e-10f) + 1e-8f);
    float e1 = 1.0f/(fmaxf(d1, 1e-10f) + 1e-8f);
    float e2 = 1.0f/(fmaxf(d2, 1e-10f) + 1e-8f);
    float inv = 1.0f/(e0 + e1 + e2);
    size_t base = ((size_t)b*N0 + n)*3;
    g_idx[base]   = i0; g_idx[base+1] = i1; g_idx[base+2] = i2;
    g_wt [base]   = e0*inv; g_wt[base+1] = e1*inv; g_wt[base+2] = e2*inv;
}

// ---------------- weight convert (elementwise, fp16) ----------------
__global__ void wconv_kernel(const float* __restrict__ w,
                             __half* __restrict__ hi, int npairs) {
    int i = blockIdx.x*blockDim.x + threadIdx.x;
    if (i >= npairs) return;
    ((uint32_t*)hi)[i] = pack_h2(w[2*i], w[2*i + 1]);
}

// ===================== fp16 mma.sync GEMM core =====================
// 512 threads, 16 warps (4 n x 4 o), CTA tile 128n x 128o, K chunk 64.
// A: fp32 LDG + in-loop fp16 convert, double-buffered smem.
// B: fp16 pre-converted, 2-stage cp.async. One __syncthreads per chunk.

__device__ __forceinline__ void issue_B(uint32_t dstbase,
    const __half* __restrict__ Wh, int ldw, int ob, int k0, int rs, int q)
{
    const __half* src = Wh + (size_t)(ob + rs)*ldw + k0 + q*16;
    uint32_t dst = dstbase + rs*PITCH_B + q*32;
    cpa16(dst, src);
    cpa16(dst + 16, src + 8);
}

template<bool BN>
__device__ __forceinline__ void conv_storeA(char* dststage, const float* ax,
                                            int kA, int rs, int q) {
    float x[16];
#pragma unroll
    for (int j = 0; j < 16; j++) x[j] = ax[j];
    if (BN) {
#pragma unroll
        for (int j = 0; j < 16; j++) {
            float v = fmaf(x[j], g_sc1[kA + j], g_bi1[kA + j]);
            x[j] = (v >= 0.f) ? v : 0.01f*v;
        }
    }
    char* arow = dststage + rs*PITCH_A + q*32;
    *(uint4*)arow = make_uint4(pack_h2(x[0], x[1]),  pack_h2(x[2], x[3]),
                               pack_h2(x[4], x[5]),  pack_h2(x[6], x[7]));
    *(uint4*)(arow + 16) = make_uint4(pack_h2(x[8], x[9]),   pack_h2(x[10], x[11]),
                                      pack_h2(x[12], x[13]), pack_h2(x[14], x[15]));
}

template<bool BN>
__device__ __forceinline__ void gemm_core(char* sm, uint32_t sb,
    const float* __restrict__ A, int ldn, int nb, int kA0,
    const __half* __restrict__ Wh, int ldw, int ob, int kW0,
    int nk64, float acc[2][4][4])
{
    int t = threadIdx.x, lane = t & 31, wid = t >> 5;
    int wn = wid & 3, wo = wid >> 2;
    int rs = t & 127, q = t >> 7;
    uint32_t aOff = (uint32_t)((wn*32 + (lane & 15))*PITCH_A + ((lane >> 4) & 1)*16);
    uint32_t bOff = (uint32_t)((wo*32 + (lane & 7) + ((lane >> 4) & 1)*8)*PITCH_B
                               + ((lane >> 3) & 1)*16);
    float ax[16];
    // ---- prologue: B(0) cp.async; A(0) LDG+convert into stage0; A(1) LDG ----
    issue_B(sb + O_B0, Wh, ldw, ob, kW0, rs, q);
    CP_COMMIT();
    {
        const float* ap = A + (size_t)(kA0 + q*16)*ldn + nb + rs;
#pragma unroll
        for (int j = 0; j < 16; j++) ax[j] = ap[(size_t)j*ldn];
    }
    conv_storeA<BN>(sm + O_A0, ax, q*16, rs, q);
    if (nk64 > 1) {
        const float* ap = A + (size_t)(kA0 + 64 + q*16)*ldn + nb + rs;
#pragma unroll
        for (int j = 0; j < 16; j++) ax[j] = ap[(size_t)j*ldn];
    }
    for (int it = 0; it < nk64; it++) {
        CP_WAIT(0);              // B(it) landed
        __syncthreads();         // A(it) STS visible; stages (it+1)&1 free
        if (it + 1 < nk64) {
            issue_B(sb + (((it + 1) & 1) ? O_B1 : O_B0), Wh, ldw, ob,
                    kW0 + (it + 1)*64, rs, q);
            CP_COMMIT();
        }
        // ---- compute chunk it: 8 independent MMAs per k16 step ----
        uint32_t aAddr = sb + ((it & 1) ? O_A1 : O_A0) + aOff;
        uint32_t bAddr = sb + ((it & 1) ? O_B1 : O_B0) + bOff;
#pragma unroll
        for (int s16 = 0; s16 < 4; s16++) {
            uint32_t Ah[2][4], Bh[2][4];
#pragma unroll
            for (int mt = 0; mt < 2; mt++)
                ldm4(Ah[mt], aAddr + mt*16*PITCH_A + s16*32);
#pragma unroll
            for (int np = 0; np < 2; np++)
                ldm4(Bh[np], bAddr + np*16*PITCH_B + s16*32);
#pragma unroll
            for (int mt = 0; mt < 2; mt++)
#pragma unroll
            for (int nt = 0; nt < 4; nt++)
                mma_f16(acc[mt][nt], Ah[mt], &Bh[nt >> 1][(nt & 1)*2]);
        }
        // ---- convert A(it+1) into other stage; LDG A(it+2) (overlap MMA drain) ----
        if (it + 1 < nk64) {
            conv_storeA<BN>(sm + (((it + 1) & 1) ? O_A1 : O_A0), ax,
                            (it + 1)*64 + q*16, rs, q);
            if (it + 2 < nk64) {
                const float* ap = A + (size_t)(kA0 + (it + 2)*64 + q*16)*ldn + nb + rs;
#pragma unroll
                for (int j = 0; j < 16; j++) ax[j] = ap[(size_t)j*ldn];
            }
        }
    }
    __syncthreads();
}

// dump one 32-o strip of accumulators into sbuf[o_local][n]
__device__ __forceinline__ void dump_strip(float* sbuf, int s, float acc[2][4][4]) {
    int t = threadIdx.x, lane = t & 31, wid = t >> 5;
    int wn = wid & 3, wo = wid >> 2;
    if (wo != s) return;
    int g = lane >> 2, c2 = (lane & 3)*2;
#pragma unroll
    for (int mt = 0; mt < 2; mt++)
#pragma unroll
    for (int nt = 0; nt < 4; nt++) {
        int nl = wn*32 + mt*16 + g;
        int ol = nt*8 + c2;
        sbuf[ol*132 + nl]         = acc[mt][nt][0];
        sbuf[(ol+1)*132 + nl]     = acc[mt][nt][1];
        sbuf[ol*132 + nl + 8]     = acc[mt][nt][2];
        sbuf[(ol+1)*132 + nl + 8] = acc[mt][nt][3];
    }
}

// ---------- GEMM 1a: Gt[b][n][o] = W1[:, :512] @ feat ----------
__global__ __launch_bounds__(512, 1)
void gemm1a_kernel(const float* __restrict__ feat) {
    extern __shared__ __align__(16) char sm[];
    uint32_t sb = smem_u32(sm);
    int b = blockIdx.z, nb = blockIdx.x*128, ob = blockIdx.y*128;
    int t = threadIdx.x;
    float acc[2][4][4] = {};
    gemm_core<false>(sm, sb, feat + (size_t)b*CPf*NP, NP, nb, 0,
                     g_W1_h, KW, ob, 0, CPf/64, acc);
    float* sbuf = (float*)(sm + O_SBUF);
    int n = t & 127, oq = t >> 7;
    for (int s = 0; s < 4; s++) {
        __syncthreads();
        dump_strip(sbuf, s, acc);
        __syncthreads();
        float f[8];
#pragma unroll
        for (int j = 0; j < 8; j++) f[j] = sbuf[(oq*8 + j)*132 + n];
        float* dst = &g_Gt[((size_t)b*NP + nb + n)*C1f + ob + s*32 + oq*8];
        *(float4*)dst       = make_float4(f[0], f[1], f[2], f[3]);
        *(float4*)(dst + 4) = make_float4(f[4], f[5], f[6], f[7]);
    }
}

// shared epilogue: optional gather, transpose writeout [o][n], BN-stat partials
__device__ __forceinline__ void epi_write(char* sm, float acc[2][4][4],
                                          float* __restrict__ Y, int nb, int ob,
                                          int b, bool gather) {
    int t = threadIdx.x;
    float* sbuf = (float*)(sm + O_SBUF);
    int*   sid  = (int*)(sm + O_SID);
    float* swt  = (float*)(sm + O_SWT);
    float* chs  = (float*)(sm + O_CHS);
    float* chq  = (float*)(sm + O_CHQ);
    if (gather) {
        for (int i = t; i < 384; i += 512) {
            size_t base = ((size_t)b*N0 + nb)*3 + i;
            sid[i] = g_idx[base]; swt[i] = g_wt[base];
        }
    }
    const float* Gt = g_Gt + (size_t)b*NP*C1f;
    for (int s = 0; s < 4; s++) {
        __syncthreads();
        dump_strip(sbuf, s, acc);
        __syncthreads();
        if (gather) {
            int n = t & 127, oq = t >> 7;
            float v[8];
#pragma unroll
            for (int j = 0; j < 8; j++) v[j] = sbuf[(oq*8 + j)*132 + n];
#pragma unroll
            for (int k = 0; k < 3; k++) {
                int   id = sid[n*3 + k];
                float wk = swt[n*3 + k];
                const float* gp = &Gt[(size_t)id*C1f + ob + s*32 + oq*8];
                float4 g0 = *(const float4*)gp;
                float4 g1 = *(const float4*)(gp + 4);
                v[0] = fmaf(wk, g0.x, v[0]); v[1] = fmaf(wk, g0.y, v[1]);
                v[2] = fmaf(wk, g0.z, v[2]); v[3] = fmaf(wk, g0.w, v[3]);
                v[4] = fmaf(wk, g1.x, v[4]); v[5] = fmaf(wk, g1.y, v[5]);
                v[6] = fmaf(wk, g1.z, v[6]); v[7] = fmaf(wk, g1.w, v[7]);
            }
#pragma unroll
            for (int j = 0; j < 8; j++) sbuf[(oq*8 + j)*132 + n] = v[j];
            __syncthreads();
        }
        {
            int ol = t >> 4, seg = t & 15, n = seg*8;
            const float* srow = &sbuf[ol*132 + n];
            float4 x0 = *(const float4*)srow;
            float4 x1 = *(const float4*)(srow + 4);
            float s1 = x0.x + x0.y + x0.z + x0.w + x1.x + x1.y + x1.z + x1.w;
            float s2 = 0.f;
            s2 = fmaf(x0.x, x0.x, s2); s2 = fmaf(x0.y, x0.y, s2);
            s2 = fmaf(x0.z, x0.z, s2); s2 = fmaf(x0.w, x0.w, s2);
            s2 = fmaf(x1.x, x1.x, s2); s2 = fmaf(x1.y, x1.y, s2);
            s2 = fmaf(x1.z, x1.z, s2); s2 = fmaf(x1.w, x1.w, s2);
            float* dst = &Y[(size_t)(ob + s*32 + ol)*N0 + nb + n];
            *(float4*)dst       = x0;
            *(float4*)(dst + 4) = x1;
#pragma unroll
            for (int off = 8; off; off >>= 1) {
                s1 += __shfl_down_sync(0xffffffffu, s1, off, 16);
                s2 += __shfl_down_sync(0xffffffffu, s2, off, 16);
            }
            if (seg == 0) { chs[s*32 + ol] = s1; chq[s*32 + ol] = s2; }
        }
    }
    __syncthreads();
    if (t < 128) {
        int pidx = blockIdx.x + 64*blockIdx.z;
        g_p1[(size_t)(ob + t)*512 + pidx] = chs[t];
        g_p2[(size_t)(ob + t)*512 + pidx] = chq[t];
    }
}

// ---- GEMM 1b: y1 = W1[:, 512:] @ skip + interp(Gt); fused stats ----
__global__ __launch_bounds__(512, 1)
void gemm1b_kernel(const float* __restrict__ skip) {
    extern __shared__ __align__(16) char sm[];
    uint32_t sb = smem_u32(sm);
    int b = blockIdx.z, nb = blockIdx.x*128, ob = blockIdx.y*128;
    float acc[2][4][4] = {};
    gemm_core<false>(sm, sb, skip + (size_t)b*CSf*N0, N0, nb, 0,
                     g_W1_h, KW, ob, CPf, CSf/64, acc);
    epi_write(sm, acc, g_y1 + (size_t)b*C1f*N0, nb, ob, b, true);
}

// ---- GEMM 2: z = W2 @ lrelu(BN1(y1)); BN on A-stage; fused stats ----
__global__ __launch_bounds__(512, 1)
void gemm2_kernel() {
    extern __shared__ __align__(16) char sm[];
    uint32_t sb = smem_u32(sm);
    int b = blockIdx.z, nb = blockIdx.x*128, ob = blockIdx.y*128;
    float acc[2][4][4] = {};
    gemm_core<true>(sm, sb, g_y1 + (size_t)b*C1f*N0, N0, nb, 0,
                    g_W2_h, C1f, ob, 0, C1f/64, acc);
    epi_write(sm, acc, g_z + (size_t)b*C2f*N0, nb, ob, b, false);
}

// ---------------- stats reduce ----------------
__global__ void stats_reduce(const float* __restrict__ gain,
                             const float* __restrict__ beta, int layer) {
    int o = blockIdx.x, t = threadIdx.x;
    const float* p1 = &g_p1[(size_t)o*512];
    const float* p2 = &g_p2[(size_t)o*512];
    float a = p1[t] + p1[t+128] + p1[t+256] + p1[t+384];
    float c = p2[t] + p2[t+128] + p2[t+256] + p2[t+384];
    __shared__ float r1[128], r2[128];
    r1[t] = a; r2[t] = c; __syncthreads();
    for (int h = 64; h > 0; h >>= 1) {
        if (t < h) { r1[t] += r1[t+h]; r2[t] += r2[t+h]; }
        __syncthreads();
    }
    if (t == 0) {
        const float invN = 1.0f/((float)BB*N0);
        float m   = r1[0]*invN;
        float var = r2[0]*invN - m*m;
        float sc  = gain[o] * (1.0f/sqrtf(var + 1e-3f));
        if (layer) { g_sc2[o] = sc; g_bi2[o] = beta[o] - m*sc; }
        else       { g_sc1[o] = sc; g_bi1[o] = beta[o] - m*sc; }
    }
}

// ---------------- output: lrelu(BN2(z)) ----------------
__global__ void out_kernel(float* __restrict__ out) {
    size_t i = (size_t)blockIdx.x*blockDim.x + threadIdx.x;
    const size_t total4 = (size_t)BB*C2f*N0/4;
    if (i >= total4) return;
    int ch = (int)((i/(N0/4)) % C2f);
    float sc = g_sc2[ch], bi = g_bi2[ch];
    float4 v = *((const float4*)g_z + i);
    v.x = fmaf(v.x, sc, bi); v.x = (v.x >= 0.f) ? v.x : 0.01f*v.x;
    v.y = fmaf(v.y, sc, bi); v.y = (v.y >= 0.f) ? v.y : 0.01f*v.y;
    v.z = fmaf(v.z, sc, bi); v.z = (v.z >= 0.f) ? v.z : 0.01f*v.z;
    v.w = fmaf(v.w, sc, bi); v.w = (v.w >= 0.f) ? v.w : 0.01f*v.w;
    *((float4*)out + i) = v;
}

// ---------------- launch ----------------
extern "C" void kernel_launch(void* const* d_in, const int* in_sizes, int n_in,
                              void* d_out, int out_size) {
    const float* xyz   = (const float*)d_in[0];
    const float* skip  = (const float*)d_in[1];
    const float* xyzp  = (const float*)d_in[2];
    const float* featp = (const float*)d_in[3];
    const float* W1    = (const float*)d_in[4];
    const float* g1    = (const float*)d_in[5];
    const float* b1    = (const float*)d_in[6];
    const float* W2    = (const float*)d_in[7];
    const float* g2    = (const float*)d_in[8];
    const float* b2    = (const float*)d_in[9];
    float* out = (float*)d_out;

    static int s_attr = 0;
    if (!s_attr) {
        cudaFuncSetAttribute(gemm1a_kernel, cudaFuncAttributeMaxDynamicSharedMemorySize, SM_BYTES);
        cudaFuncSetAttribute(gemm1b_kernel, cudaFuncAttributeMaxDynamicSharedMemorySize, SM_BYTES);
        cudaFuncSetAttribute(gemm2_kernel,  cudaFuncAttributeMaxDynamicSharedMemorySize, SM_BYTES);
        s_attr = 1;
    }

    __half *w1_h, *w2_h;
    cudaGetSymbolAddress((void**)&w1_h, g_W1_h);
    cudaGetSymbolAddress((void**)&w2_h, g_W2_h);

    const size_t xyz_elems = (size_t)BB*3*N0;
    const size_t nf_elems  = (size_t)BB*C2f*N0;
    size_t off = 0;
    if ((size_t)out_size >= xyz_elems + nf_elems) {
        cudaMemcpyAsync(out, xyz, xyz_elems*sizeof(float), cudaMemcpyDeviceToDevice);
        off = xyz_elems;
    }

    knn_kernel   <<<dim3(N0/256, BB), 256>>>(xyz, xyzp);
    wconv_kernel <<<(C1f*KW/2 + 255)/256,  256>>>(W1, w1_h, C1f*KW/2);
    wconv_kernel <<<(C2f*C1f/2 + 255)/256, 256>>>(W2, w2_h, C2f*C1f/2);
    gemm1a_kernel<<<dim3(NP/128, C1f/128, BB), 512, SM_BYTES>>>(featp);
    gemm1b_kernel<<<dim3(N0/128, C1f/128, BB), 512, SM_BYTES>>>(skip);
    stats_reduce <<<C1f, 128>>>(g1, b1, 0);
    gemm2_kernel <<<dim3(N0/128, C2f/128, BB), 512, SM_BYTES>>>();
    stats_reduce <<<C2f, 128>>>(g2, b2, 1);
    out_kernel   <<<(unsigned)((nf_elems/4 + 255)/256), 256>>>(out + off);
}